// round 1
// baseline (speedup 1.0000x reference)
#include <cuda_runtime.h>
#include <math.h>

// Problem constants
#define BB 64
#define CC 512
#define SS 512
#define EE 257
#define LK 128
#define HK 129
#define EP 260            // padded E (multiple of 4)
#define MTOT (BB*CC)      // 32768
#define NW  (4*EP)        // 1040  (lowr, lowi, highr, highi planes)
#define LXW (2*EP)        // 520   (low_x real, imag planes)
#define KIR (2*EP)        // 520   irfft K dim
#define PS  ((size_t)BB*CC*CC)   // score plane stride = 16,777,216

#define INV_SQRT_S 0.04419417382415922f   // 1/sqrt(512)
#define TWO_PI_OVER_S 0.01227184630308513f
#define ATTN_SCALE 0.06237828615518053f   // 1/sqrt(257)

// ---------------- scratch (static device globals; no allocation) -------------
__device__ float g_Wt[512 * NW];          // rfft∘proj weights, [s][plane*EP+e]
__device__ float g_bias[NW];              // combined biases
__device__ float g_C[KIR * SS];           // irfft matrix rows: [0..259]=Cr, [260..519]=Ci
__device__ float g_low[(size_t)MTOT * NW];   // projections, [m][plane*EP+e]
__device__ float g_S[4 * PS];                // scores / probs, 4 planes
__device__ float g_X[(size_t)MTOT * LXW];    // low_x, [m][plane*EP+e]

// ---------------- weight builders --------------------------------------------

// One block per s (512 blocks). Computes Wl = F[:, :LK] @ l1, Wh = F[:, LK:] @ h1.
__global__ void build_w_kernel(const float* __restrict__ l1r, const float* __restrict__ l1i,
                               const float* __restrict__ h1r, const float* __restrict__ h1i)
{
    __shared__ float cr[257], ci[257];
    int s = blockIdx.x;
    for (int k = threadIdx.x; k < 257; k += blockDim.x) {
        int idx = (s * k) & 511;
        float ang = (float)idx * TWO_PI_OVER_S;
        float sn, cs;
        sincosf(ang, &sn, &cs);
        cr[k] = cs * INV_SQRT_S;       // Re exp(-i ang)
        ci[k] = -sn * INV_SQRT_S;      // Im exp(-i ang)
    }
    __syncthreads();
    for (int e = threadIdx.x; e < EP; e += blockDim.x) {
        float wlr = 0.f, wli = 0.f, whr = 0.f, whi = 0.f;
        if (e < EE) {
            for (int k = 0; k < LK; k++) {
                float ar = cr[k], ai = ci[k];
                float br = l1r[k * EE + e], bi = l1i[k * EE + e];
                wlr += ar * br - ai * bi;
                wli += ar * bi + ai * br;
            }
            for (int k = 0; k < HK; k++) {
                float ar = cr[LK + k], ai = ci[LK + k];
                float br = h1r[k * EE + e], bi = h1i[k * EE + e];
                whr += ar * br - ai * bi;
                whi += ar * bi + ai * br;
            }
        }
        float* w = g_Wt + (size_t)s * NW;
        w[0 * EP + e] = wlr;
        w[1 * EP + e] = wli;
        w[2 * EP + e] = whr;
        w[3 * EP + e] = whi;
    }
}

__global__ void build_bias_kernel(const float* __restrict__ lbr, const float* __restrict__ lbi,
                                  const float* __restrict__ hbr, const float* __restrict__ hbi)
{
    int n = blockIdx.x * blockDim.x + threadIdx.x;
    if (n >= NW) return;
    int plane = n / EP, e = n - plane * EP;
    float v = 0.f;
    if (e < EE) {
        const float* src = (plane == 0) ? lbr : (plane == 1) ? lbi : (plane == 2) ? hbr : hbi;
        v = src[e];
    }
    g_bias[n] = v;
}

__global__ void build_c_kernel()
{
    int idx = blockIdx.x * blockDim.x + threadIdx.x;
    if (idx >= KIR * SS) return;
    int r = idx / SS, s = idx - r * SS;
    int e = (r < EP) ? r : r - EP;
    float v = 0.f;
    if (e < EE) {
        float w = (e == 0 || e == 256) ? 1.f : 2.f;
        float ang = (float)((e * s) & 511) * TWO_PI_OVER_S;
        float sn, cs;
        sincosf(ang, &sn, &cs);
        v = (r < EP) ? (w * cs * INV_SQRT_S) : (-w * sn * INV_SQRT_S);
    }
    g_C[idx] = v;
}

// ---------------- tiled GEMM core (64x64x16, 256 threads, 4x4/thread) --------

template <bool BT, bool TWO>
__device__ __forceinline__ void gemm_core(
    const float* __restrict__ A1, const float* __restrict__ B1,
    const float* __restrict__ A2, const float* __restrict__ B2,
    int lda, int ldb, int K, int nrem,
    float (&acc1)[4][4], float (&acc2)[4][4])
{
    __shared__ float As[TWO ? 2 : 1][16][68];
    __shared__ float Bs[TWO ? 2 : 1][16][68];
    const int t = threadIdx.x;
    const int tx = t & 15, ty = t >> 4;
    const int am = t >> 2, akq = (t & 3) << 2;   // A: 64 rows x float4 along k
    const int bk = t >> 4, bnq = (t & 15) << 2;  // B NN: 16 k rows x float4 along n
    const int bn = t >> 2, bkq = (t & 3) << 2;   // B NT: 64 n rows x float4 along k

    for (int k0 = 0; k0 < K; k0 += 16) {
        {   // A tiles
            int kk = k0 + akq;
            float4 v = make_float4(0.f, 0.f, 0.f, 0.f);
            if (kk < K) v = *(const float4*)(A1 + (size_t)am * lda + kk);
            As[0][akq + 0][am] = v.x; As[0][akq + 1][am] = v.y;
            As[0][akq + 2][am] = v.z; As[0][akq + 3][am] = v.w;
            if (TWO) {
                float4 w = make_float4(0.f, 0.f, 0.f, 0.f);
                if (kk < K) w = *(const float4*)(A2 + (size_t)am * lda + kk);
                As[1][akq + 0][am] = w.x; As[1][akq + 1][am] = w.y;
                As[1][akq + 2][am] = w.z; As[1][akq + 3][am] = w.w;
            }
        }
        if (!BT) {   // B row-major K x N
            int kk = k0 + bk;
            float4 v = make_float4(0.f, 0.f, 0.f, 0.f);
            if (kk < K && bnq < nrem) v = *(const float4*)(B1 + (size_t)kk * ldb + bnq);
            *(float4*)&Bs[0][bk][bnq] = v;
            if (TWO) {
                float4 w = make_float4(0.f, 0.f, 0.f, 0.f);
                if (kk < K && bnq < nrem) w = *(const float4*)(B2 + (size_t)kk * ldb + bnq);
                *(float4*)&Bs[1][bk][bnq] = w;
            }
        } else {     // B row-major N x K (dot of rows)
            int kk = k0 + bkq;
            float4 v = make_float4(0.f, 0.f, 0.f, 0.f);
            if (kk < K) v = *(const float4*)(B1 + (size_t)bn * ldb + kk);
            Bs[0][bkq + 0][bn] = v.x; Bs[0][bkq + 1][bn] = v.y;
            Bs[0][bkq + 2][bn] = v.z; Bs[0][bkq + 3][bn] = v.w;
            if (TWO) {
                float4 w = make_float4(0.f, 0.f, 0.f, 0.f);
                if (kk < K) w = *(const float4*)(B2 + (size_t)bn * ldb + kk);
                Bs[1][bkq + 0][bn] = w.x; Bs[1][bkq + 1][bn] = w.y;
                Bs[1][bkq + 2][bn] = w.z; Bs[1][bkq + 3][bn] = w.w;
            }
        }
        __syncthreads();
#pragma unroll
        for (int k = 0; k < 16; k++) {
            float4 a = *(const float4*)&As[0][k][ty << 2];
            float4 b = *(const float4*)&Bs[0][k][tx << 2];
            float ar[4] = {a.x, a.y, a.z, a.w}, br[4] = {b.x, b.y, b.z, b.w};
#pragma unroll
            for (int i = 0; i < 4; i++)
#pragma unroll
                for (int j = 0; j < 4; j++)
                    acc1[i][j] = fmaf(ar[i], br[j], acc1[i][j]);
            if (TWO) {
                float4 a2 = *(const float4*)&As[1][k][ty << 2];
                float4 b2 = *(const float4*)&Bs[1][k][tx << 2];
                float ar2[4] = {a2.x, a2.y, a2.z, a2.w}, br2[4] = {b2.x, b2.y, b2.z, b2.w};
#pragma unroll
                for (int i = 0; i < 4; i++)
#pragma unroll
                    for (int j = 0; j < 4; j++)
                        acc2[i][j] = fmaf(ar2[i], br2[j], acc2[i][j]);
            }
        }
        __syncthreads();
    }
}

// ---------------- GEMM kernels -----------------------------------------------

// low/high projections: relu(x @ W + bias), fused across 4 planes. N=1040.
__global__ __launch_bounds__(256, 2) void proj_kernel(const float* __restrict__ x)
{
    int n0 = blockIdx.x * 64, m0 = blockIdx.y * 64;
    float acc1[4][4] = {}, acc2[4][4] = {};
    int nrem = NW - n0; if (nrem > 64) nrem = 64;
    gemm_core<false, false>(x + (size_t)m0 * SS, g_Wt + n0, nullptr, nullptr,
                            SS, NW, SS, nrem, acc1, acc2);
    int tx = threadIdx.x & 15, ty = threadIdx.x >> 4;
#pragma unroll
    for (int i = 0; i < 4; i++) {
        int row = m0 + (ty << 2) + i;
#pragma unroll
        for (int j = 0; j < 4; j++) {
            int col = n0 + (tx << 2) + j;
            if (col < NW)
                g_low[(size_t)row * NW + col] = fmaxf(acc1[i][j] + g_bias[col], 0.f);
        }
    }
}

// Attention scores: 4 complex combos per batch. z = b*4 + combo.
__global__ __launch_bounds__(256, 2) void score_kernel()
{
    int z = blockIdx.z;
    int b = z >> 2, combo = z & 3;
    const float* base = g_low + (size_t)b * CC * NW;
    int a1o, b1o, a2o, b2o; float sign;
    if (combo == 0)      { a1o = 0; b1o = 0;      a2o = EP; b2o = EP;     sign = -1.f; } // S1r
    else if (combo == 1) { a1o = 0; b1o = EP;     a2o = EP; b2o = 0;      sign =  1.f; } // S1i
    else if (combo == 2) { a1o = 0; b1o = 2 * EP; a2o = EP; b2o = 3 * EP; sign = -1.f; } // S2r
    else                 { a1o = 0; b1o = 3 * EP; a2o = EP; b2o = 2 * EP; sign =  1.f; } // S2i
    int m0 = blockIdx.y * 64, n0 = blockIdx.x * 64;
    float acc1[4][4] = {}, acc2[4][4] = {};
    gemm_core<true, true>(base + a1o + (size_t)m0 * NW, base + b1o + (size_t)n0 * NW,
                          base + a2o + (size_t)m0 * NW, base + b2o + (size_t)n0 * NW,
                          NW, NW, EP, 64, acc1, acc2);
    float* out = g_S + (size_t)combo * PS + (size_t)b * CC * CC;
    int tx = threadIdx.x & 15, ty = threadIdx.x >> 4;
#pragma unroll
    for (int i = 0; i < 4; i++) {
        int row = m0 + (ty << 2) + i;
#pragma unroll
        for (int j = 0; j < 4; j++) {
            int col = n0 + (tx << 2) + j;
            out[(size_t)row * CC + col] = (acc1[i][j] + sign * acc2[i][j]) * ATTN_SCALE;
        }
    }
}

// Row softmax + combine: plane0 <- sm(plane0)+sm(plane2), plane1 <- sm(plane1)+sm(plane3).
__global__ void softmax_kernel()
{
    int warp = (blockIdx.x * blockDim.x + threadIdx.x) >> 5;
    int lane = threadIdx.x & 31;
    size_t base = (size_t)(warp >> 9) * CC * CC + (size_t)(warp & 511) * CC;
#pragma unroll
    for (int pp = 0; pp < 2; pp++) {
        float* p1 = g_S + (size_t)pp * PS + base;
        float* p2 = g_S + (size_t)(pp + 2) * PS + base;
        float v1[16], v2[16];
#pragma unroll
        for (int u = 0; u < 16; u++) { v1[u] = p1[lane + u * 32]; v2[u] = p2[lane + u * 32]; }
        float m1 = -3.4e38f, m2 = -3.4e38f;
#pragma unroll
        for (int u = 0; u < 16; u++) { m1 = fmaxf(m1, v1[u]); m2 = fmaxf(m2, v2[u]); }
#pragma unroll
        for (int o = 16; o; o >>= 1) {
            m1 = fmaxf(m1, __shfl_xor_sync(0xffffffffu, m1, o));
            m2 = fmaxf(m2, __shfl_xor_sync(0xffffffffu, m2, o));
        }
        float s1 = 0.f, s2 = 0.f;
#pragma unroll
        for (int u = 0; u < 16; u++) {
            v1[u] = expf(v1[u] - m1); s1 += v1[u];
            v2[u] = expf(v2[u] - m2); s2 += v2[u];
        }
#pragma unroll
        for (int o = 16; o; o >>= 1) {
            s1 += __shfl_xor_sync(0xffffffffu, s1, o);
            s2 += __shfl_xor_sync(0xffffffffu, s2, o);
        }
        float r1 = 1.f / s1, r2 = 1.f / s2;
#pragma unroll
        for (int u = 0; u < 16; u++)
            p1[lane + u * 32] = v1[u] * r1 + v2[u] * r2;
    }
}

// low_x = P @ low (complex). z = b*2 + plane(real/imag).
__global__ __launch_bounds__(256, 2) void attnv_kernel()
{
    int z = blockIdx.z;
    int b = z >> 1, pl = z & 1;
    int m0 = blockIdx.y * 64, n0 = blockIdx.x * 64;
    const float* Pr = g_S + (size_t)b * CC * CC + (size_t)m0 * CC;
    const float* Pi = g_S + PS + (size_t)b * CC * CC + (size_t)m0 * CC;
    const float* lowbase = g_low + (size_t)b * CC * NW;
    const float *B1, *B2; float sign;
    if (pl == 0) { B1 = lowbase + 0;  B2 = lowbase + EP; sign = -1.f; }  // Pr@lr - Pi@li
    else         { B1 = lowbase + EP; B2 = lowbase + 0;  sign =  1.f; }  // Pr@li + Pi@lr
    int nrem = EP - n0; if (nrem > 64) nrem = 64;
    float acc1[4][4] = {}, acc2[4][4] = {};
    gemm_core<false, true>(Pr, B1 + n0, Pi, B2 + n0, CC, NW, CC, nrem, acc1, acc2);
    int tx = threadIdx.x & 15, ty = threadIdx.x >> 4;
#pragma unroll
    for (int i = 0; i < 4; i++) {
        int row = b * CC + m0 + (ty << 2) + i;
#pragma unroll
        for (int j = 0; j < 4; j++) {
            int col = n0 + (tx << 2) + j;
            if (col < EP)
                g_X[(size_t)row * LXW + pl * EP + col] = acc1[i][j] + sign * acc2[i][j];
        }
    }
}

// out = low_x @ [Cr; Ci]  (irfft as one real GEMM, K=520).
__global__ __launch_bounds__(256, 2) void irfft_kernel(float* __restrict__ out)
{
    int n0 = blockIdx.x * 64, m0 = blockIdx.y * 64;
    float acc1[4][4] = {}, acc2[4][4] = {};
    gemm_core<false, false>(g_X + (size_t)m0 * LXW, g_C + n0, nullptr, nullptr,
                            LXW, SS, KIR, 64, acc1, acc2);
    int tx = threadIdx.x & 15, ty = threadIdx.x >> 4;
#pragma unroll
    for (int i = 0; i < 4; i++) {
        int row = m0 + (ty << 2) + i;
#pragma unroll
        for (int j = 0; j < 4; j++) {
            int col = n0 + (tx << 2) + j;
            out[(size_t)row * SS + col] = acc1[i][j];
        }
    }
}

// ---------------- launch ------------------------------------------------------

extern "C" void kernel_launch(void* const* d_in, const int* in_sizes, int n_in,
                              void* d_out, int out_size)
{
    const float* x   = (const float*)d_in[0];
    const float* l1r = (const float*)d_in[1];
    const float* l1i = (const float*)d_in[2];
    const float* h1r = (const float*)d_in[3];
    const float* h1i = (const float*)d_in[4];
    const float* lbr = (const float*)d_in[5];
    const float* lbi = (const float*)d_in[6];
    const float* hbr = (const float*)d_in[7];
    const float* hbi = (const float*)d_in[8];
    float* out = (float*)d_out;

    build_w_kernel<<<512, 256>>>(l1r, l1i, h1r, h1i);
    build_bias_kernel<<<(NW + 255) / 256, 256>>>(lbr, lbi, hbr, hbi);
    build_c_kernel<<<(KIR * SS + 255) / 256, 256>>>();

    proj_kernel<<<dim3((NW + 63) / 64, MTOT / 64), 256>>>(x);           // (17, 512)
    score_kernel<<<dim3(CC / 64, CC / 64, BB * 4), 256>>>();            // (8, 8, 256)
    softmax_kernel<<<MTOT / 8, 256>>>();                                // warp per row
    attnv_kernel<<<dim3((EP + 63) / 64, CC / 64, BB * 2), 256>>>();     // (5, 8, 128)
    irfft_kernel<<<dim3(SS / 64, MTOT / 64), 256>>>(out);               // (8, 512)
}

// round 2
// speedup vs baseline: 1.2560x; 1.2560x over previous
#include <cuda_runtime.h>
#include <math.h>

// Problem constants
#define BB 64
#define CC 512
#define SS 512
#define EE 257
#define EP 260                      // padded E (multiple of 4)
#define LK 128
#define HK 129
#define MTOT (BB*CC)                // 32768
#define NW  1040                    // 4*EP projection planes (lr, li, hr, hi)
#define LXW 520                     // low_x width (2 planes)
#define PSL ((size_t)MTOT*EP)       // low plane stride
#define PS  ((size_t)BB*CC*CC)      // score plane stride

#define INV_SQRT_S 0.04419417382415922f   // 1/sqrt(512)
#define TWO_PI_OVER_S 0.01227184630308513f
#define ATTN_SCALE 0.06237828615518053f   // 1/sqrt(257)

// ---------------- scratch (static device globals; no allocation) -------------
__device__ float g_Wt[512 * NW];            // rfft∘proj weights [s][plane*EP+e]
__device__ float g_bias[NW];
__device__ float g_C[LXW * SS];             // irfft matrix [r][s]
__device__ float g_low[6 * PSL];            // planes: lr, li, hr, hi, ls=lr+li, hs=hr+hi
__device__ float g_S[6 * PS];               // score planes t1,t2,t3,u1,u2,u3 -> then Pr,Pi in 0,1
__device__ float g_X[(size_t)MTOT * LXW];   // low_x [m][pl*EP+e]

// ---------------- weight builders --------------------------------------------

__global__ void build_w_kernel(const float* __restrict__ l1r, const float* __restrict__ l1i,
                               const float* __restrict__ h1r, const float* __restrict__ h1i)
{
    __shared__ float cr[257], ci[257];
    int s = blockIdx.x;
    for (int k = threadIdx.x; k < 257; k += blockDim.x) {
        int idx = (s * k) & 511;
        float ang = (float)idx * TWO_PI_OVER_S;
        float sn, cs;
        sincosf(ang, &sn, &cs);
        cr[k] = cs * INV_SQRT_S;
        ci[k] = -sn * INV_SQRT_S;
    }
    __syncthreads();
    for (int e = threadIdx.x; e < EP; e += blockDim.x) {
        float wlr = 0.f, wli = 0.f, whr = 0.f, whi = 0.f;
        if (e < EE) {
            for (int k = 0; k < LK; k++) {
                float ar = cr[k], ai = ci[k];
                float br = l1r[k * EE + e], bi = l1i[k * EE + e];
                wlr += ar * br - ai * bi;
                wli += ar * bi + ai * br;
            }
            for (int k = 0; k < HK; k++) {
                float ar = cr[LK + k], ai = ci[LK + k];
                float br = h1r[k * EE + e], bi = h1i[k * EE + e];
                whr += ar * br - ai * bi;
                whi += ar * bi + ai * br;
            }
        }
        float* w = g_Wt + (size_t)s * NW;
        w[0 * EP + e] = wlr;
        w[1 * EP + e] = wli;
        w[2 * EP + e] = whr;
        w[3 * EP + e] = whi;
    }
}

__global__ void build_bias_kernel(const float* __restrict__ lbr, const float* __restrict__ lbi,
                                  const float* __restrict__ hbr, const float* __restrict__ hbi)
{
    int n = blockIdx.x * blockDim.x + threadIdx.x;
    if (n >= NW) return;
    int plane = n / EP, e = n - plane * EP;
    float v = 0.f;
    if (e < EE) {
        const float* src = (plane == 0) ? lbr : (plane == 1) ? lbi : (plane == 2) ? hbr : hbi;
        v = src[e];
    }
    g_bias[n] = v;
}

__global__ void build_c_kernel()
{
    int idx = blockIdx.x * blockDim.x + threadIdx.x;
    if (idx >= LXW * SS) return;
    int r = idx / SS, s = idx - r * SS;
    int e = (r < EP) ? r : r - EP;
    float v = 0.f;
    if (e < EE) {
        float w = (e == 0 || e == 256) ? 1.f : 2.f;
        float ang = (float)((e * s) & 511) * TWO_PI_OVER_S;
        float sn, cs;
        sincosf(ang, &sn, &cs);
        v = (r < EP) ? (w * cs * INV_SQRT_S) : (-w * sn * INV_SQRT_S);
    }
    g_C[idx] = v;
}

// ---------------- SGEMM core: 128x128x8 tile, 256 threads, 8x8 per thread ----
// A: row-major [M x K] (k contiguous). BT=false: B row-major [K x N].
// BT=true: B row-major [N x K] (dot of rows). sign folded into A tile.
// Requires: M tile rows fully valid; K % 4 == 0; nvalid % 4 == 0 (BT=false).

template <bool BT>
__device__ __forceinline__ void gpass(
    float (*As)[132], float (*Bs)[132],
    const float* __restrict__ A, const float* __restrict__ B,
    int lda, int ldb, int K, int nvalid, float sign,
    float (&acc)[8][8])
{
    const int t = threadIdx.x;
    const int tx = t & 15, ty = t >> 4;
    const int am = t >> 1, akq = (t & 1) << 2;   // 128 rows x one float4 along k
    const int bk = t >> 5, bnq = (t & 31) << 2;  // (!BT) 8 k-rows x float4 along n

    for (int k0 = 0; k0 < K; k0 += 8) {
        {
            int kk = k0 + akq;
            float4 v = make_float4(0.f, 0.f, 0.f, 0.f);
            if (kk < K) v = *(const float4*)(A + (size_t)am * lda + kk);
            As[akq + 0][am] = v.x * sign;
            As[akq + 1][am] = v.y * sign;
            As[akq + 2][am] = v.z * sign;
            As[akq + 3][am] = v.w * sign;
        }
        if (BT) {
            int kk = k0 + akq;
            float4 v = make_float4(0.f, 0.f, 0.f, 0.f);
            if (kk < K) v = *(const float4*)(B + (size_t)am * ldb + kk);
            Bs[akq + 0][am] = v.x;
            Bs[akq + 1][am] = v.y;
            Bs[akq + 2][am] = v.z;
            Bs[akq + 3][am] = v.w;
        } else {
            int kb = k0 + bk;
            float4 v = make_float4(0.f, 0.f, 0.f, 0.f);
            if (kb < K && bnq < nvalid) v = *(const float4*)(B + (size_t)kb * ldb + bnq);
            *(float4*)&Bs[bk][bnq] = v;
        }
        __syncthreads();
#pragma unroll
        for (int k = 0; k < 8; k++) {
            float4 a0 = *(const float4*)&As[k][ty << 2];
            float4 a1 = *(const float4*)&As[k][(ty << 2) + 64];
            float4 b0 = *(const float4*)&Bs[k][tx << 2];
            float4 b1 = *(const float4*)&Bs[k][(tx << 2) + 64];
            float av[8] = {a0.x, a0.y, a0.z, a0.w, a1.x, a1.y, a1.z, a1.w};
            float bv[8] = {b0.x, b0.y, b0.z, b0.w, b1.x, b1.y, b1.z, b1.w};
#pragma unroll
            for (int i = 0; i < 8; i++)
#pragma unroll
                for (int j = 0; j < 8; j++)
                    acc[i][j] = fmaf(av[i], bv[j], acc[i][j]);
        }
        __syncthreads();
    }
}

__device__ __forceinline__ int emap(int base, int q, int i) { return base + (q << 2) + (i & 3) + ((i >> 2) << 6); }

// ---------------- GEMM kernels -----------------------------------------------

// relu(x @ W + bias) -> 4 planes of g_low
__global__ __launch_bounds__(256, 2) void proj_kernel(const float* __restrict__ x)
{
    __shared__ float As[8][132], Bs[8][132];
    int n0 = blockIdx.x * 128, m0 = blockIdx.y * 128;
    int nvalid = NW - n0; if (nvalid > 128) nvalid = 128;
    float acc[8][8] = {};
    gpass<false>(As, Bs, x + (size_t)m0 * SS, g_Wt + n0, SS, NW, SS, nvalid, 1.f, acc);
    int tx = threadIdx.x & 15, ty = threadIdx.x >> 4;
#pragma unroll
    for (int i = 0; i < 8; i++) {
        int row = emap(m0, ty, i);
#pragma unroll
        for (int j = 0; j < 8; j++) {
            int col = emap(n0, tx, j);
            if (col < NW) {
                int p = col / EP, e = col - p * EP;
                g_low[(size_t)p * PSL + (size_t)row * EP + e] =
                    fmaxf(acc[i][j] + g_bias[col], 0.f);
            }
        }
    }
}

// build sum planes: ls = lr + li, hs = hr + hi
__global__ void sum_kernel()
{
    size_t i = (size_t)blockIdx.x * blockDim.x + threadIdx.x;
    size_t n4 = PSL / 4;
    if (i >= n4) return;
    const float4* r = (const float4*)g_low;
    float4* w = (float4*)g_low;
    float4 a = r[i], b = r[n4 + i];
    float4 c = r[2 * n4 + i], d = r[3 * n4 + i];
    w[4 * n4 + i] = make_float4(a.x + b.x, a.y + b.y, a.z + b.z, a.w + b.w);
    w[5 * n4 + i] = make_float4(c.x + d.x, c.y + d.y, c.z + d.z, c.w + d.w);
}

// Karatsuba score planes: t1=lr@lr', t2=li@li', t3=ls@ls', u1=lr@hr', u2=li@hi', u3=ls@hs'
__global__ __launch_bounds__(256, 2) void score_kernel()
{
    __shared__ float As[8][132], Bs[8][132];
    int z = blockIdx.z;
    int b = z / 6, which = z - b * 6;
    int hi = (which >= 3) ? 1 : 0;
    int w = which - 3 * hi;
    int apn = (w == 2) ? 4 : w;
    int bpn = hi ? ((w == 2) ? 5 : w + 2) : apn;
    int m0 = blockIdx.y * 128, n0 = blockIdx.x * 128;
    const float* A  = g_low + (size_t)apn * PSL + ((size_t)b * CC + m0) * EP;
    const float* Bm = g_low + (size_t)bpn * PSL + ((size_t)b * CC + n0) * EP;
    float acc[8][8] = {};
    gpass<true>(As, Bs, A, Bm, EP, EP, EP, 128, 1.f, acc);
    float* out = g_S + (size_t)which * PS + (size_t)b * CC * CC;
    int tx = threadIdx.x & 15, ty = threadIdx.x >> 4;
#pragma unroll
    for (int i = 0; i < 8; i++) {
        int row = emap(m0, ty, i);
#pragma unroll
        for (int j = 0; j < 8; j++)
            out[(size_t)row * CC + emap(n0, tx, j)] = acc[i][j];
    }
}

__device__ __forceinline__ void softmax16(float (&v)[16], int lane)
{
    float m = -3.4e38f;
#pragma unroll
    for (int u = 0; u < 16; u++) m = fmaxf(m, v[u]);
#pragma unroll
    for (int o = 16; o; o >>= 1) m = fmaxf(m, __shfl_xor_sync(0xffffffffu, m, o));
    float s = 0.f;
#pragma unroll
    for (int u = 0; u < 16; u++) { v[u] = expf(v[u] - m); s += v[u]; }
#pragma unroll
    for (int o = 16; o; o >>= 1) s += __shfl_xor_sync(0xffffffffu, s, o);
    float r = 1.f / s;
#pragma unroll
    for (int u = 0; u < 16; u++) v[u] *= r;
}

// Karatsuba combine + 4 softmaxes + combine probs. One warp per row.
__global__ void softmax_kernel()
{
    int gw = (blockIdx.x * blockDim.x + threadIdx.x) >> 5;   // global row (b*512+m)
    int lane = threadIdx.x & 31;
    size_t base = (size_t)gw * CC;
    float t1[16], t2[16], t3[16], sr[16], si[16], pr[16], pi[16];

    // attention 1 (planes 0,1,2)
#pragma unroll
    for (int u = 0; u < 16; u++) {
        int c = lane + u * 32;
        t1[u] = g_S[0 * PS + base + c];
        t2[u] = g_S[1 * PS + base + c];
        t3[u] = g_S[2 * PS + base + c];
    }
#pragma unroll
    for (int u = 0; u < 16; u++) {
        sr[u] = (t1[u] - t2[u]) * ATTN_SCALE;
        si[u] = (t3[u] - t1[u] - t2[u]) * ATTN_SCALE;
    }
    softmax16(sr, lane);
    softmax16(si, lane);
#pragma unroll
    for (int u = 0; u < 16; u++) { pr[u] = sr[u]; pi[u] = si[u]; }

    // attention 2 (planes 3,4,5)
#pragma unroll
    for (int u = 0; u < 16; u++) {
        int c = lane + u * 32;
        t1[u] = g_S[3 * PS + base + c];
        t2[u] = g_S[4 * PS + base + c];
        t3[u] = g_S[5 * PS + base + c];
    }
#pragma unroll
    for (int u = 0; u < 16; u++) {
        sr[u] = (t1[u] - t2[u]) * ATTN_SCALE;
        si[u] = (t3[u] - t1[u] - t2[u]) * ATTN_SCALE;
    }
    softmax16(sr, lane);
    softmax16(si, lane);
#pragma unroll
    for (int u = 0; u < 16; u++) {
        int c = lane + u * 32;
        g_S[0 * PS + base + c] = pr[u] + sr[u];
        g_S[1 * PS + base + c] = pi[u] + si[u];
    }
}

// low_x = P @ low (complex): xr = Pr@vr - Pi@vi, xi = Pr@vi + Pi@vr
__global__ __launch_bounds__(256, 2) void attnv_kernel()
{
    __shared__ float As[8][132], Bs[8][132];
    int z = blockIdx.z;
    int b = z >> 1, pl = z & 1;
    int m0 = blockIdx.y * 128, n0 = blockIdx.x * 128;
    int nvalid = EP - n0; if (nvalid > 128) nvalid = 128;
    const float* Pr = g_S + ((size_t)b * CC + m0) * CC;
    const float* Pi = g_S + PS + ((size_t)b * CC + m0) * CC;
    const float* vr = g_low + 0 * PSL + (size_t)b * CC * EP + n0;
    const float* vi = g_low + 1 * PSL + (size_t)b * CC * EP + n0;
    float acc[8][8] = {};
    if (pl == 0) {
        gpass<false>(As, Bs, Pr, vr, CC, EP, CC, nvalid, 1.f, acc);
        gpass<false>(As, Bs, Pi, vi, CC, EP, CC, nvalid, -1.f, acc);
    } else {
        gpass<false>(As, Bs, Pr, vi, CC, EP, CC, nvalid, 1.f, acc);
        gpass<false>(As, Bs, Pi, vr, CC, EP, CC, nvalid, 1.f, acc);
    }
    int tx = threadIdx.x & 15, ty = threadIdx.x >> 4;
#pragma unroll
    for (int i = 0; i < 8; i++) {
        int row = b * CC + emap(m0, ty, i);
#pragma unroll
        for (int j = 0; j < 8; j++) {
            int col = emap(n0, tx, j);
            if (col < EP)
                g_X[(size_t)row * LXW + pl * EP + col] = acc[i][j];
        }
    }
}

// out = low_x @ C  (irfft as one real GEMM, K=520)
__global__ __launch_bounds__(256, 2) void irfft_kernel(float* __restrict__ out)
{
    __shared__ float As[8][132], Bs[8][132];
    int n0 = blockIdx.x * 128, m0 = blockIdx.y * 128;
    float acc[8][8] = {};
    gpass<false>(As, Bs, g_X + (size_t)m0 * LXW, g_C + n0, LXW, SS, LXW, 128, 1.f, acc);
    int tx = threadIdx.x & 15, ty = threadIdx.x >> 4;
#pragma unroll
    for (int i = 0; i < 8; i++) {
        int row = emap(m0, ty, i);
#pragma unroll
        for (int j = 0; j < 8; j++)
            out[(size_t)row * SS + emap(n0, tx, j)] = acc[i][j];
    }
}

// ---------------- launch ------------------------------------------------------

extern "C" void kernel_launch(void* const* d_in, const int* in_sizes, int n_in,
                              void* d_out, int out_size)
{
    const float* x   = (const float*)d_in[0];
    const float* l1r = (const float*)d_in[1];
    const float* l1i = (const float*)d_in[2];
    const float* h1r = (const float*)d_in[3];
    const float* h1i = (const float*)d_in[4];
    const float* lbr = (const float*)d_in[5];
    const float* lbi = (const float*)d_in[6];
    const float* hbr = (const float*)d_in[7];
    const float* hbi = (const float*)d_in[8];
    float* out = (float*)d_out;

    build_w_kernel<<<512, 256>>>(l1r, l1i, h1r, h1i);
    build_bias_kernel<<<(NW + 255) / 256, 256>>>(lbr, lbi, hbr, hbi);
    build_c_kernel<<<(LXW * SS + 255) / 256, 256>>>();

    proj_kernel<<<dim3(9, MTOT / 128), 256>>>(x);               // (9, 256)
    sum_kernel<<<(int)((PSL / 4 + 255) / 256), 256>>>();
    score_kernel<<<dim3(4, 4, BB * 6), 256>>>();                // (4, 4, 384)
    softmax_kernel<<<MTOT / 8, 256>>>();
    attnv_kernel<<<dim3(3, 4, BB * 2), 256>>>();                // (3, 4, 128)
    irfft_kernel<<<dim3(4, MTOT / 128), 256>>>(out);            // (4, 256)
}

// round 4
// speedup vs baseline: 2.8912x; 2.3020x over previous
#include <cuda_runtime.h>
#include <cuda_fp16.h>
#include <cstdint>
#include <math.h>

// ---------------- problem constants ----------------
#define BB 64
#define CC 512
#define SS 512
#define EE 257
#define MTOT (BB*CC)                 // 32768
#define KP  320                      // low-plane row stride (score K, mult of 64)
#define PSL ((size_t)MTOT*KP)
#define PLW 288                      // plane width in proj-N space
#define NWP 1152                     // proj N = 4*288
#define XW  576                      // X row stride / irfft K
#define PS  ((size_t)BB*CC*CC)

#define INV_SQRT_S 0.04419417382415922f
#define TWO_PI_OVER_S 0.01227184630308513f
#define ATTN_SCALE 0.06237828615518053f   // 1/sqrt(257)

// ---------------- scratch (static device globals) ----------------
__device__ __align__(256) float g_bias[NWP];
__device__ __align__(256) float g_S[6*PS];
__device__ __align__(256) __half g_xh[(size_t)MTOT*SS];
__device__ __align__(256) __half g_xl[(size_t)MTOT*SS];
__device__ __align__(256) __half g_WTh[NWP*SS];
__device__ __align__(256) __half g_WTl[NWP*SS];
__device__ __align__(256) __half g_CT[SS*XW];
__device__ __align__(256) __half g_lowh[6*PSL];
__device__ __align__(256) __half g_lowl[6*PSL];
__device__ __align__(256) __half g_P[(size_t)MTOT*1024];
__device__ __align__(256) __half g_vt[(size_t)BB*2*PLW*1024];
__device__ __align__(256) __half g_X[(size_t)MTOT*XW];

// ---------------- helpers ----------------
__device__ __forceinline__ uint32_t smem_u32(const void* p) {
    uint32_t a;
    asm("{ .reg .u64 t; cvta.to.shared.u64 t, %1; cvt.u32.u64 %0, t; }" : "=r"(a) : "l"(p));
    return a;
}
__device__ __forceinline__ void hsplit(float v, __half* h, __half* l) {
    __half a = __float2half_rn(v);
    *h = a;
    *l = __float2half_rn(v - __half2float(a));
}
__device__ __forceinline__ void ldsm4(uint32_t (&r)[4], uint32_t a) {
    asm volatile("ldmatrix.sync.aligned.m8n8.x4.shared.b16 {%0,%1,%2,%3}, [%4];"
                 : "=r"(r[0]), "=r"(r[1]), "=r"(r[2]), "=r"(r[3]) : "r"(a));
}
__device__ __forceinline__ void ldsm2(uint32_t (&r)[2], uint32_t a) {
    asm volatile("ldmatrix.sync.aligned.m8n8.x2.shared.b16 {%0,%1}, [%2];"
                 : "=r"(r[0]), "=r"(r[1]) : "r"(a));
}
__device__ __forceinline__ void mma16816(float (&d)[4], const uint32_t (&a)[4], const uint32_t (&b)[2]) {
    asm volatile(
        "mma.sync.aligned.m16n8k16.row.col.f32.f16.f16.f32 "
        "{%0,%1,%2,%3},{%4,%5,%6,%7},{%8,%9},{%0,%1,%2,%3};"
        : "+f"(d[0]), "+f"(d[1]), "+f"(d[2]), "+f"(d[3])
        : "r"(a[0]), "r"(a[1]), "r"(a[2]), "r"(a[3]), "r"(b[0]), "r"(b[1]));
}
__device__ __forceinline__ void cpasync16(uint32_t s, const void* g) {
    asm volatile("cp.async.cg.shared.global [%0], [%1], 16;" :: "r"(s), "l"(g));
}

// ---------------- builder kernels ----------------

__global__ void split_x_kernel(const float* __restrict__ x)
{
    size_t i = (size_t)blockIdx.x * blockDim.x + threadIdx.x;
    if (i >= (size_t)MTOT * SS) return;
    hsplit(x[i], &g_xh[i], &g_xl[i]);
}

__global__ void build_w_kernel(const float* __restrict__ l1r, const float* __restrict__ l1i,
                               const float* __restrict__ h1r, const float* __restrict__ h1i)
{
    __shared__ float cr[257], ci[257];
    int s = blockIdx.x;
    for (int k = threadIdx.x; k < 257; k += blockDim.x) {
        int idx = (s * k) & 511;
        float ang = (float)idx * TWO_PI_OVER_S;
        float sn, cs;
        sincosf(ang, &sn, &cs);
        cr[k] = cs * INV_SQRT_S;
        ci[k] = -sn * INV_SQRT_S;
    }
    __syncthreads();
    for (int e = threadIdx.x; e < EE; e += blockDim.x) {
        float wlr = 0.f, wli = 0.f, whr = 0.f, whi = 0.f;
        for (int k = 0; k < 128; k++) {
            float ar = cr[k], ai = ci[k];
            float br = l1r[k * EE + e], bi = l1i[k * EE + e];
            wlr += ar * br - ai * bi;
            wli += ar * bi + ai * br;
        }
        for (int k = 0; k < 129; k++) {
            float ar = cr[128 + k], ai = ci[128 + k];
            float br = h1r[k * EE + e], bi = h1i[k * EE + e];
            whr += ar * br - ai * bi;
            whi += ar * bi + ai * br;
        }
        hsplit(wlr, &g_WTh[(0 * PLW + e) * SS + s], &g_WTl[(0 * PLW + e) * SS + s]);
        hsplit(wli, &g_WTh[(1 * PLW + e) * SS + s], &g_WTl[(1 * PLW + e) * SS + s]);
        hsplit(whr, &g_WTh[(2 * PLW + e) * SS + s], &g_WTl[(2 * PLW + e) * SS + s]);
        hsplit(whi, &g_WTh[(3 * PLW + e) * SS + s], &g_WTl[(3 * PLW + e) * SS + s]);
    }
}

__global__ void build_bias_kernel(const float* __restrict__ lbr, const float* __restrict__ lbi,
                                  const float* __restrict__ hbr, const float* __restrict__ hbi)
{
    int n = blockIdx.x * blockDim.x + threadIdx.x;
    if (n >= NWP) return;
    int p = n / PLW, e = n - p * PLW;
    float v = 0.f;
    if (e < EE) {
        const float* src = (p == 0) ? lbr : (p == 1) ? lbi : (p == 2) ? hbr : hbi;
        v = src[e];
    }
    g_bias[n] = v;
}

// CT[s][k]: k<260 -> w*cos(e=k), 288<=k<548 -> -w*sin(e=k-288), else 0. single fp16
__global__ void build_ct_kernel()
{
    int idx = blockIdx.x * blockDim.x + threadIdx.x;
    if (idx >= SS * XW) return;
    int s = idx / XW, k = idx - s * XW;
    float v = 0.f;
    int e = -1, im = 0;
    if (k < 260) { e = k; im = 0; }
    else if (k >= 288 && k < 548) { e = k - 288; im = 1; }
    if (e >= 0 && e < EE) {
        float w = (e == 0 || e == 256) ? 1.f : 2.f;
        float ang = (float)((e * s) & 511) * TWO_PI_OVER_S;
        float sn, cs;
        sincosf(ang, &sn, &cs);
        v = im ? (-w * sn * INV_SQRT_S) : (w * cs * INV_SQRT_S);
    }
    g_CT[idx] = __float2half_rn(v);
}

// zero pad regions: WT rows e in [257,288) and low planes 0..3 cols e in [288,320)
__global__ void pad_wt_kernel()
{
    int idx = blockIdx.x * blockDim.x + threadIdx.x;
    if (idx >= 4 * 31 * SS) return;
    int p = idx / (31 * SS), rem = idx - p * 31 * SS;
    int e = 257 + rem / SS, s = rem % SS;
    g_WTh[(p * PLW + e) * SS + s] = __float2half_rn(0.f);
    g_WTl[(p * PLW + e) * SS + s] = __float2half_rn(0.f);
}
__global__ void pad_low_kernel()
{
    size_t idx = (size_t)blockIdx.x * blockDim.x + threadIdx.x;
    if (idx >= (size_t)4 * MTOT * 32) return;
    size_t p = idx / ((size_t)MTOT * 32), rem = idx - p * (size_t)MTOT * 32;
    size_t row = rem >> 5;
    int e = 288 + (int)(rem & 31);
    size_t d = p * PSL + row * KP + e;
    g_lowh[d] = __float2half_rn(0.f);
    g_lowl[d] = __float2half_rn(0.f);
}

// sum planes: ls = lr+li (4), hs = hr+hi (5)
__global__ void sum_kernel()
{
    size_t i = (size_t)blockIdx.x * blockDim.x + threadIdx.x;
    if (i >= PSL) return;
    float lr = __half2float(g_lowh[0 * PSL + i]) + __half2float(g_lowl[0 * PSL + i]);
    float li = __half2float(g_lowh[1 * PSL + i]) + __half2float(g_lowl[1 * PSL + i]);
    float hr = __half2float(g_lowh[2 * PSL + i]) + __half2float(g_lowl[2 * PSL + i]);
    float hi = __half2float(g_lowh[3 * PSL + i]) + __half2float(g_lowl[3 * PSL + i]);
    hsplit(lr + li, &g_lowh[4 * PSL + i], &g_lowl[4 * PSL + i]);
    hsplit(hr + hi, &g_lowh[5 * PSL + i], &g_lowl[5 * PSL + i]);
}

// build vt: vt[b][0][n][k] = [vrT | -viT], vt[b][1][n][k] = [viT | vrT]; n<288, k<1024
__global__ void vt_kernel()
{
    __shared__ float tr[32][33], ti[32][33];
    int b = blockIdx.z, e0 = blockIdx.y * 32, c0 = blockIdx.x * 32;
    int tx = threadIdx.x, ty = threadIdx.y;
    for (int r = ty; r < 32; r += 8) {
        size_t src = ((size_t)(b * CC + c0 + r)) * KP + (e0 + tx);
        tr[r][tx] = __half2float(g_lowh[0 * PSL + src]) + __half2float(g_lowl[0 * PSL + src]);
        ti[r][tx] = __half2float(g_lowh[1 * PSL + src]) + __half2float(g_lowl[1 * PSL + src]);
    }
    __syncthreads();
    for (int r = ty; r < 32; r += 8) {
        int n = e0 + r, c = c0 + tx;
        float lr = tr[tx][r], li = ti[tx][r];
        size_t d0 = ((size_t)(b * 2 + 0) * PLW + n) * 1024;
        size_t d1 = ((size_t)(b * 2 + 1) * PLW + n) * 1024;
        g_vt[d0 + c]       = __float2half_rn(lr);
        g_vt[d0 + 512 + c] = __float2half_rn(-li);
        g_vt[d1 + c]       = __float2half_rn(li);
        g_vt[d1 + 512 + c] = __float2half_rn(lr);
    }
}

// ---------------- HMMA GEMM core: 128x128 tile, 8 warps, K-chunk 64 ----------------

struct GArgs {
    const __half* A[3];
    const __half* B[3];
    int npass, kpp, lda, ldb, bvalid;
};

__device__ __forceinline__ void gload(const GArgs& g, int ch, int stg, uint32_t base, int t)
{
    int p = ch / g.kpp, kc = ch - p * g.kpp;
    const __half* Ap = g.A[p] + kc * 64;
    const __half* Bp = g.B[p] + kc * 64;
    int r = t >> 1, c4 = (t & 1) * 4;
    int rb = (r < g.bvalid) ? r : (g.bvalid - 1);
    const __half* ga = Ap + (size_t)r * g.lda + c4 * 8;
    const __half* gb = Bp + (size_t)rb * g.ldb + c4 * 8;
    uint32_t sA = base + (uint32_t)stg * 32768u + (uint32_t)r * 128u;
    uint32_t sB = sA + 16384u;
#pragma unroll
    for (int i = 0; i < 4; i++) {
        int c = c4 + i;
        uint32_t sw = (uint32_t)((c ^ (r & 7)) << 4);
        cpasync16(sA + sw, ga + i * 8);
        cpasync16(sB + sw, gb + i * 8);
    }
    asm volatile("cp.async.commit_group;");
}

__device__ __forceinline__ void gemm_run(const GArgs& g, float (&acc)[4][4][4], uint32_t base)
{
    const int t = threadIdx.x;
    const int nch = g.npass * g.kpp;
    const int warp = t >> 5, lane = t & 31;
    const int wr = warp >> 2, wc = warp & 3;

    gload(g, 0, 0, base, t);
    for (int ch = 0; ch < nch; ch++) {
        int stg = ch & 1;
        if (ch + 1 < nch) {
            gload(g, ch + 1, stg ^ 1, base, t);
            asm volatile("cp.async.wait_group 1;");
        } else {
            asm volatile("cp.async.wait_group 0;");
        }
        __syncthreads();
        uint32_t sA = base + (uint32_t)stg * 32768u;
        uint32_t sB = sA + 16384u;
#pragma unroll
        for (int s = 0; s < 4; s++) {
            uint32_t a[4][4], b[4][2];
#pragma unroll
            for (int mt = 0; mt < 4; mt++) {
                int row = wr * 64 + mt * 16 + (lane & 15);
                int u = s * 2 + (lane >> 4);
                ldsm4(a[mt], sA + (uint32_t)row * 128u + (uint32_t)((u ^ (row & 7)) << 4));
            }
#pragma unroll
            for (int nt = 0; nt < 4; nt++) {
                int row = wc * 32 + nt * 8 + (lane & 7);
                int u = s * 2 + ((lane >> 3) & 1);
                ldsm2(b[nt], sB + (uint32_t)row * 128u + (uint32_t)((u ^ (row & 7)) << 4));
            }
#pragma unroll
            for (int mt = 0; mt < 4; mt++)
#pragma unroll
                for (int nt = 0; nt < 4; nt++)
                    mma16816(acc[mt][nt], a[mt], b[nt]);
        }
        __syncthreads();
    }
}

#define GEMM_PRE() \
    extern __shared__ char dynsm[]; \
    uint32_t raw = smem_u32(dynsm); \
    uint32_t base = (raw + 127u) & ~127u; \
    float acc[4][4][4]; \
    for (int i = 0; i < 4; i++) for (int j = 0; j < 4; j++) for (int q = 0; q < 4; q++) acc[i][j][q] = 0.f; \
    const int warp = threadIdx.x >> 5, lane = threadIdx.x & 31; \
    const int wr = warp >> 2, wc = warp & 3; \
    const int gr = lane >> 2, gc = lane & 3;

#define MMA_SMEM (65536 + 128)

// ---------------- proj: relu(x@W + bias) -> split low planes ----------------
__global__ __launch_bounds__(256, 2) void proj_mma()
{
    GEMM_PRE();
    int n0 = blockIdx.x * 128, m0 = blockIdx.y * 128;
    GArgs g;
    g.A[0] = g_xh + (size_t)m0 * SS;  g.B[0] = g_WTh + (size_t)n0 * SS;
    g.A[1] = g_xh + (size_t)m0 * SS;  g.B[1] = g_WTl + (size_t)n0 * SS;
    g.A[2] = g_xl + (size_t)m0 * SS;  g.B[2] = g_WTh + (size_t)n0 * SS;
    g.npass = 3; g.kpp = 8; g.lda = SS; g.ldb = SS; g.bvalid = 128;
    gemm_run(g, acc, base);
#pragma unroll
    for (int mt = 0; mt < 4; mt++) {
#pragma unroll
        for (int nt = 0; nt < 4; nt++) {
            int col = n0 + wc * 32 + nt * 8 + gc * 2;
            int p = col / PLW, e = col - p * PLW;
            float b0 = g_bias[col], b1 = g_bias[col + 1];
#pragma unroll
            for (int h = 0; h < 2; h++) {
                int row = m0 + wr * 64 + mt * 16 + gr + h * 8;
                float v0 = fmaxf(acc[mt][nt][h * 2 + 0] + b0, 0.f);
                float v1 = fmaxf(acc[mt][nt][h * 2 + 1] + b1, 0.f);
                size_t d = (size_t)p * PSL + (size_t)row * KP + e;
                hsplit(v0, &g_lowh[d], &g_lowl[d]);
                hsplit(v1, &g_lowh[d + 1], &g_lowl[d + 1]);
            }
        }
    }
}

// ---------------- score: 6 Karatsuba planes -> g_S fp32 ----------------
__global__ __launch_bounds__(256, 2) void score_mma()
{
    GEMM_PRE();
    int z = blockIdx.z;
    int b = z / 6, which = z - b * 6;
    int hi = (which >= 3) ? 1 : 0;
    int w = which - 3 * hi;
    int apn = (w == 2) ? 4 : w;
    int bpn = hi ? ((w == 2) ? 5 : w + 2) : apn;
    int m0 = blockIdx.y * 128, n0 = blockIdx.x * 128;
    size_t aoff = (size_t)apn * PSL + (size_t)(b * CC + m0) * KP;
    size_t boff = (size_t)bpn * PSL + (size_t)(b * CC + n0) * KP;
    GArgs g;
    g.A[0] = g_lowh + aoff;  g.B[0] = g_lowh + boff;
    g.A[1] = g_lowh + aoff;  g.B[1] = g_lowl + boff;
    g.A[2] = g_lowl + aoff;  g.B[2] = g_lowh + boff;
    g.npass = 3; g.kpp = 5; g.lda = KP; g.ldb = KP; g.bvalid = 128;
    gemm_run(g, acc, base);
    float* out = g_S + (size_t)which * PS + (size_t)(b * CC) * CC;
#pragma unroll
    for (int mt = 0; mt < 4; mt++) {
#pragma unroll
        for (int nt = 0; nt < 4; nt++) {
            int col = n0 + wc * 32 + nt * 8 + gc * 2;
#pragma unroll
            for (int h = 0; h < 2; h++) {
                int row = m0 + wr * 64 + mt * 16 + gr + h * 8;
                *(float2*)&out[(size_t)row * CC + col] =
                    make_float2(acc[mt][nt][h * 2 + 0], acc[mt][nt][h * 2 + 1]);
            }
        }
    }
}

// ---------------- softmax + Karatsuba combine -> P fp16 [Pr|Pi] ----------------
__device__ __forceinline__ void softmax16(float (&v)[16])
{
    float m = -3.4e38f;
#pragma unroll
    for (int u = 0; u < 16; u++) m = fmaxf(m, v[u]);
#pragma unroll
    for (int o = 16; o; o >>= 1) m = fmaxf(m, __shfl_xor_sync(0xffffffffu, m, o));
    float s = 0.f;
#pragma unroll
    for (int u = 0; u < 16; u++) { v[u] = expf(v[u] - m); s += v[u]; }
#pragma unroll
    for (int o = 16; o; o >>= 1) s += __shfl_xor_sync(0xffffffffu, s, o);
    float r = 1.f / s;
#pragma unroll
    for (int u = 0; u < 16; u++) v[u] *= r;
}

__global__ void softmax_kernel()
{
    int gw = (blockIdx.x * blockDim.x + threadIdx.x) >> 5;
    int lane = threadIdx.x & 31;
    size_t base = (size_t)gw * CC;
    float t1[16], t2[16], t3[16], sr[16], si[16], pr[16], pi[16];
#pragma unroll
    for (int u = 0; u < 16; u++) {
        int c = lane + u * 32;
        t1[u] = g_S[0 * PS + base + c];
        t2[u] = g_S[1 * PS + base + c];
        t3[u] = g_S[2 * PS + base + c];
    }
#pragma unroll
    for (int u = 0; u < 16; u++) {
        sr[u] = (t1[u] - t2[u]) * ATTN_SCALE;
        si[u] = (t3[u] - t1[u] - t2[u]) * ATTN_SCALE;
    }
    softmax16(sr);
    softmax16(si);
#pragma unroll
    for (int u = 0; u < 16; u++) { pr[u] = sr[u]; pi[u] = si[u]; }
#pragma unroll
    for (int u = 0; u < 16; u++) {
        int c = lane + u * 32;
        t1[u] = g_S[3 * PS + base + c];
        t2[u] = g_S[4 * PS + base + c];
        t3[u] = g_S[5 * PS + base + c];
    }
#pragma unroll
    for (int u = 0; u < 16; u++) {
        sr[u] = (t1[u] - t2[u]) * ATTN_SCALE;
        si[u] = (t3[u] - t1[u] - t2[u]) * ATTN_SCALE;
    }
    softmax16(sr);
    softmax16(si);
#pragma unroll
    for (int u = 0; u < 16; u++) {
        int c = lane + u * 32;
        size_t d = (size_t)gw * 1024 + c;
        g_P[d]       = __float2half_rn(pr[u] + sr[u]);
        g_P[d + 512] = __float2half_rn(pi[u] + si[u]);
    }
}

// ---------------- attnv: X = P @ vt^T (single fp16, K=1024) ----------------
__global__ __launch_bounds__(256, 2) void attnv_mma()
{
    GEMM_PRE();
    int z = blockIdx.z;
    int b = z >> 1, pl = z & 1;
    int n0 = blockIdx.x * 128, m0 = blockIdx.y * 128;
    int bv = PLW - n0; if (bv > 128) bv = 128;
    GArgs g;
    g.A[0] = g_P + (size_t)(b * CC + m0) * 1024;
    g.B[0] = g_vt + ((size_t)(b * 2 + pl) * PLW + n0) * 1024;
    g.npass = 1; g.kpp = 16; g.lda = 1024; g.ldb = 1024; g.bvalid = bv;
    gemm_run(g, acc, base);
#pragma unroll
    for (int mt = 0; mt < 4; mt++) {
#pragma unroll
        for (int nt = 0; nt < 4; nt++) {
            int col = n0 + wc * 32 + nt * 8 + gc * 2;
            if (col >= PLW) continue;
#pragma unroll
            for (int h = 0; h < 2; h++) {
                int row = m0 + wr * 64 + mt * 16 + gr + h * 8;
                size_t d = (size_t)(b * CC + row) * XW + (size_t)pl * PLW + col;
                __half2 v = __floats2half2_rn(acc[mt][nt][h * 2 + 0], acc[mt][nt][h * 2 + 1]);
                *(__half2*)&g_X[d] = v;
            }
        }
    }
}

// ---------------- irfft: out = X @ CT^T (single fp16, K=576) ----------------
__global__ __launch_bounds__(256, 2) void irfft_mma(float* __restrict__ out)
{
    GEMM_PRE();
    int n0 = blockIdx.x * 128, m0 = blockIdx.y * 128;
    GArgs g;
    g.A[0] = g_X + (size_t)m0 * XW;
    g.B[0] = g_CT + (size_t)n0 * XW;
    g.npass = 1; g.kpp = 9; g.lda = XW; g.ldb = XW; g.bvalid = 128;
    gemm_run(g, acc, base);
#pragma unroll
    for (int mt = 0; mt < 4; mt++) {
#pragma unroll
        for (int nt = 0; nt < 4; nt++) {
            int col = n0 + wc * 32 + nt * 8 + gc * 2;
#pragma unroll
            for (int h = 0; h < 2; h++) {
                int row = m0 + wr * 64 + mt * 16 + gr + h * 8;
                *(float2*)&out[(size_t)row * SS + col] =
                    make_float2(acc[mt][nt][h * 2 + 0], acc[mt][nt][h * 2 + 1]);
            }
        }
    }
}

// ---------------- launch ----------------

extern "C" void kernel_launch(void* const* d_in, const int* in_sizes, int n_in,
                              void* d_out, int out_size)
{
    const float* x   = (const float*)d_in[0];
    const float* l1r = (const float*)d_in[1];
    const float* l1i = (const float*)d_in[2];
    const float* h1r = (const float*)d_in[3];
    const float* h1i = (const float*)d_in[4];
    const float* lbr = (const float*)d_in[5];
    const float* lbi = (const float*)d_in[6];
    const float* hbr = (const float*)d_in[7];
    const float* hbi = (const float*)d_in[8];
    float* out = (float*)d_out;

    cudaFuncSetAttribute(proj_mma,  cudaFuncAttributeMaxDynamicSharedMemorySize, MMA_SMEM);
    cudaFuncSetAttribute(score_mma, cudaFuncAttributeMaxDynamicSharedMemorySize, MMA_SMEM);
    cudaFuncSetAttribute(attnv_mma, cudaFuncAttributeMaxDynamicSharedMemorySize, MMA_SMEM);
    cudaFuncSetAttribute(irfft_mma, cudaFuncAttributeMaxDynamicSharedMemorySize, MMA_SMEM);

    split_x_kernel<<<(int)(((size_t)MTOT * SS + 255) / 256), 256>>>(x);
    build_w_kernel<<<512, 256>>>(l1r, l1i, h1r, h1i);
    build_bias_kernel<<<(NWP + 255) / 256, 256>>>(lbr, lbi, hbr, hbi);
    build_ct_kernel<<<(SS * XW + 255) / 256, 256>>>();
    pad_wt_kernel<<<(4 * 31 * SS + 255) / 256, 256>>>();
    pad_low_kernel<<<(int)(((size_t)4 * MTOT * 32 + 255) / 256), 256>>>();

    proj_mma<<<dim3(NWP / 128, MTOT / 128), 256, MMA_SMEM>>>();      // (9, 256)
    sum_kernel<<<(int)((PSL + 255) / 256), 256>>>();
    vt_kernel<<<dim3(CC / 32, PLW / 32, BB), dim3(32, 8)>>>();
    score_mma<<<dim3(4, 4, BB * 6), 256, MMA_SMEM>>>();              // (4, 4, 384)
    softmax_kernel<<<MTOT / 8, 256>>>();
    attnv_mma<<<dim3(3, 4, BB * 2), 256, MMA_SMEM>>>();              // (3, 4, 128)
    irfft_mma<<<dim3(4, MTOT / 128), 256, MMA_SMEM>>>(out);          // (4, 256)
}

// round 5
// speedup vs baseline: 3.2271x; 1.1162x over previous
#include <cuda_runtime.h>
#include <cuda_fp16.h>
#include <cstdint>
#include <math.h>

// ---------------- problem constants ----------------
#define BB 64
#define CC 512
#define SS 512
#define EE 257
#define MTOT (BB*CC)                 // 32768
#define KP  320                      // low-plane row stride
#define PSL ((size_t)MTOT*KP)
#define PLW 288                      // plane width in proj-N space
#define NWP 1152                     // proj N = 4*288
#define XW  512                      // packed X row stride / irfft K
#define PS  ((size_t)BB*CC*CC)

#define INV_SQRT_S 0.04419417382415922f
#define TWO_PI_OVER_S 0.01227184630308513f
#define ATTN_SCALE 0.06237828615518053f   // 1/sqrt(257)

// ---------------- scratch (static device globals) ----------------
__device__ __align__(256) float g_bias[NWP];
__device__ __align__(256) float g_S[6*PS];
__device__ __align__(256) float g_Xny[MTOT];          // xr at e=256
__device__ __align__(256) float g_vny[BB*CC*2];       // (vr,vi) at e=256
__device__ __align__(256) __half g_xh[(size_t)MTOT*SS];
__device__ __align__(256) __half g_xl[(size_t)MTOT*SS];
__device__ __align__(256) __half g_WTh[NWP*SS];
__device__ __align__(256) __half g_WTl[NWP*SS];
__device__ __align__(256) __half g_CT[SS*XW];
__device__ __align__(256) __half g_lowh[6*PSL];
__device__ __align__(256) __half g_lowl[6*PSL];
__device__ __align__(256) __half g_P[(size_t)MTOT*1024];
__device__ __align__(256) __half g_vt[(size_t)BB*2*256*1024];
__device__ __align__(256) __half g_X[(size_t)MTOT*XW];

// ---------------- helpers ----------------
__device__ __forceinline__ uint32_t smem_u32(const void* p) {
    uint32_t a;
    asm("{ .reg .u64 t; cvta.to.shared.u64 t, %1; cvt.u32.u64 %0, t; }" : "=r"(a) : "l"(p));
    return a;
}
__device__ __forceinline__ void hsplit(float v, __half* h, __half* l) {
    __half a = __float2half_rn(v);
    *h = a;
    *l = __float2half_rn(v - __half2float(a));
}
__device__ __forceinline__ void ldsm4(uint32_t (&r)[4], uint32_t a) {
    asm volatile("ldmatrix.sync.aligned.m8n8.x4.shared.b16 {%0,%1,%2,%3}, [%4];"
                 : "=r"(r[0]), "=r"(r[1]), "=r"(r[2]), "=r"(r[3]) : "r"(a));
}
__device__ __forceinline__ void ldsm2(uint32_t (&r)[2], uint32_t a) {
    asm volatile("ldmatrix.sync.aligned.m8n8.x2.shared.b16 {%0,%1}, [%2];"
                 : "=r"(r[0]), "=r"(r[1]) : "r"(a));
}
__device__ __forceinline__ void mma16816(float (&d)[4], const uint32_t (&a)[4], const uint32_t (&b)[2]) {
    asm volatile(
        "mma.sync.aligned.m16n8k16.row.col.f32.f16.f16.f32 "
        "{%0,%1,%2,%3},{%4,%5,%6,%7},{%8,%9},{%0,%1,%2,%3};"
        : "+f"(d[0]), "+f"(d[1]), "+f"(d[2]), "+f"(d[3])
        : "r"(a[0]), "r"(a[1]), "r"(a[2]), "r"(a[3]), "r"(b[0]), "r"(b[1]));
}
__device__ __forceinline__ void cpasync16(uint32_t s, const void* g) {
    asm volatile("cp.async.cg.shared.global [%0], [%1], 16;" :: "r"(s), "l"(g));
}
__device__ __forceinline__ float low256(int plane, int grow) {
    size_t d = (size_t)plane * PSL + (size_t)grow * KP + 256;
    return __half2float(g_lowh[d]) + __half2float(g_lowl[d]);
}
__device__ __forceinline__ float plane256(int pn, int grow) {
    if (pn == 4) return low256(0, grow) + low256(1, grow);
    if (pn == 5) return low256(2, grow) + low256(3, grow);
    return low256(pn, grow);
}

// ---------------- builder kernels ----------------

__global__ void split_x_kernel(const float* __restrict__ x)
{
    size_t i = (size_t)blockIdx.x * blockDim.x + threadIdx.x;
    if (i >= (size_t)MTOT * SS) return;
    hsplit(x[i], &g_xh[i], &g_xl[i]);
}

__global__ void build_w_kernel(const float* __restrict__ l1r, const float* __restrict__ l1i,
                               const float* __restrict__ h1r, const float* __restrict__ h1i)
{
    __shared__ float cr[257], ci[257];
    int s = blockIdx.x;
    for (int k = threadIdx.x; k < 257; k += blockDim.x) {
        int idx = (s * k) & 511;
        float ang = (float)idx * TWO_PI_OVER_S;
        float sn, cs;
        sincosf(ang, &sn, &cs);
        cr[k] = cs * INV_SQRT_S;
        ci[k] = -sn * INV_SQRT_S;
    }
    __syncthreads();
    for (int e = threadIdx.x; e < EE; e += blockDim.x) {
        float wlr = 0.f, wli = 0.f, whr = 0.f, whi = 0.f;
        for (int k = 0; k < 128; k++) {
            float ar = cr[k], ai = ci[k];
            float br = l1r[k * EE + e], bi = l1i[k * EE + e];
            wlr += ar * br - ai * bi;
            wli += ar * bi + ai * br;
        }
        for (int k = 0; k < 129; k++) {
            float ar = cr[128 + k], ai = ci[128 + k];
            float br = h1r[k * EE + e], bi = h1i[k * EE + e];
            whr += ar * br - ai * bi;
            whi += ar * bi + ai * br;
        }
        hsplit(wlr, &g_WTh[(0 * PLW + e) * SS + s], &g_WTl[(0 * PLW + e) * SS + s]);
        hsplit(wli, &g_WTh[(1 * PLW + e) * SS + s], &g_WTl[(1 * PLW + e) * SS + s]);
        hsplit(whr, &g_WTh[(2 * PLW + e) * SS + s], &g_WTl[(2 * PLW + e) * SS + s]);
        hsplit(whi, &g_WTh[(3 * PLW + e) * SS + s], &g_WTl[(3 * PLW + e) * SS + s]);
    }
}

__global__ void build_bias_kernel(const float* __restrict__ lbr, const float* __restrict__ lbi,
                                  const float* __restrict__ hbr, const float* __restrict__ hbi)
{
    int n = blockIdx.x * blockDim.x + threadIdx.x;
    if (n >= NWP) return;
    int p = n / PLW, e = n - p * PLW;
    float v = 0.f;
    if (e < EE) {
        const float* src = (p == 0) ? lbr : (p == 1) ? lbi : (p == 2) ? hbr : hbi;
        v = src[e];
    }
    g_bias[n] = v;
}

// packed CT[s][k]: k<256 -> w*cos(e=k), k>=256 -> -w*sin(e=k-256) (e=0 -> 0)
__global__ void build_ct_kernel()
{
    int idx = blockIdx.x * blockDim.x + threadIdx.x;
    if (idx >= SS * XW) return;
    int s = idx / XW, k = idx - s * XW;
    float v;
    if (k < 256) {
        int e = k;
        float w = (e == 0) ? 1.f : 2.f;
        float ang = (float)((e * s) & 511) * TWO_PI_OVER_S;
        v = w * cosf(ang) * INV_SQRT_S;
    } else {
        int e = k - 256;
        if (e == 0) v = 0.f;
        else {
            float ang = (float)((e * s) & 511) * TWO_PI_OVER_S;
            v = -2.f * sinf(ang) * INV_SQRT_S;
        }
    }
    g_CT[idx] = __float2half_rn(v);
}

// zero pad WT rows e in [257,288)
__global__ void pad_wt_kernel()
{
    int idx = blockIdx.x * blockDim.x + threadIdx.x;
    if (idx >= 4 * 31 * SS) return;
    int p = idx / (31 * SS), rem = idx - p * 31 * SS;
    int e = 257 + rem / SS, s = rem % SS;
    g_WTh[(p * PLW + e) * SS + s] = __float2half_rn(0.f);
    g_WTl[(p * PLW + e) * SS + s] = __float2half_rn(0.f);
}

// sum planes: ls = lr+li (4), hs = hr+hi (5)
__global__ void sum_kernel()
{
    size_t i = (size_t)blockIdx.x * blockDim.x + threadIdx.x;
    if (i >= PSL) return;
    float lr = __half2float(g_lowh[0 * PSL + i]) + __half2float(g_lowl[0 * PSL + i]);
    float li = __half2float(g_lowh[1 * PSL + i]) + __half2float(g_lowl[1 * PSL + i]);
    float hr = __half2float(g_lowh[2 * PSL + i]) + __half2float(g_lowl[2 * PSL + i]);
    float hi = __half2float(g_lowh[3 * PSL + i]) + __half2float(g_lowl[3 * PSL + i]);
    hsplit(lr + li, &g_lowh[4 * PSL + i], &g_lowl[4 * PSL + i]);
    hsplit(hr + hi, &g_lowh[5 * PSL + i], &g_lowl[5 * PSL + i]);
}

// vny[b][c] = (vr[c,256], vi[c,256]) fp32
__global__ void vny_kernel()
{
    int i = blockIdx.x * blockDim.x + threadIdx.x;
    if (i >= BB * CC) return;
    size_t r = (size_t)i * KP + 256;
    g_vny[2 * i]     = __half2float(g_lowh[r]) + __half2float(g_lowl[r]);
    g_vny[2 * i + 1] = __half2float(g_lowh[PSL + r]) + __half2float(g_lowl[PSL + r]);
}

// packed vt: vt[b][0][n][k] = [vr | -vi], vt[b][1][n][k] = [vi | vr]; n<256, k<1024
__global__ void vt_kernel()
{
    __shared__ float tr[32][33], ti[32][33];
    int b = blockIdx.z, e0 = blockIdx.y * 32, c0 = blockIdx.x * 32;
    int tx = threadIdx.x, ty = threadIdx.y;
    for (int r = ty; r < 32; r += 8) {
        size_t src = ((size_t)(b * CC + c0 + r)) * KP + (e0 + tx);
        tr[r][tx] = __half2float(g_lowh[0 * PSL + src]) + __half2float(g_lowl[0 * PSL + src]);
        ti[r][tx] = __half2float(g_lowh[1 * PSL + src]) + __half2float(g_lowl[1 * PSL + src]);
    }
    __syncthreads();
    for (int r = ty; r < 32; r += 8) {
        int n = e0 + r, c = c0 + tx;
        float lr = tr[tx][r], li = ti[tx][r];
        size_t d0 = ((size_t)(b * 2 + 0) * 256 + n) * 1024;
        size_t d1 = ((size_t)(b * 2 + 1) * 256 + n) * 1024;
        g_vt[d0 + c]       = __float2half_rn(lr);
        g_vt[d0 + 512 + c] = __float2half_rn(-li);
        g_vt[d1 + c]       = __float2half_rn(li);
        g_vt[d1 + 512 + c] = __float2half_rn(lr);
    }
}

// ---------------- HMMA GEMM core: 128x128 tile, 8 warps, K-chunk 64 ----------------

struct GArgs {
    const __half* A[3];
    const __half* B[3];
    int npass, kpp, lda, ldb, bvalid;
};

__device__ __forceinline__ void gload(const GArgs& g, int ch, int stg, uint32_t base, int t)
{
    int p = ch / g.kpp, kc = ch - p * g.kpp;
    const __half* Ap = g.A[p] + kc * 64;
    const __half* Bp = g.B[p] + kc * 64;
    int r = t >> 1, c4 = (t & 1) * 4;
    int rb = (r < g.bvalid) ? r : (g.bvalid - 1);
    const __half* ga = Ap + (size_t)r * g.lda + c4 * 8;
    const __half* gb = Bp + (size_t)rb * g.ldb + c4 * 8;
    uint32_t sA = base + (uint32_t)stg * 32768u + (uint32_t)r * 128u;
    uint32_t sB = sA + 16384u;
#pragma unroll
    for (int i = 0; i < 4; i++) {
        int c = c4 + i;
        uint32_t sw = (uint32_t)((c ^ (r & 7)) << 4);
        cpasync16(sA + sw, ga + i * 8);
        cpasync16(sB + sw, gb + i * 8);
    }
    asm volatile("cp.async.commit_group;");
}

__device__ __forceinline__ void gemm_run(const GArgs& g, float (&acc)[4][4][4], uint32_t base)
{
    const int t = threadIdx.x;
    const int nch = g.npass * g.kpp;
    const int warp = t >> 5, lane = t & 31;
    const int wr = warp >> 2, wc = warp & 3;

    gload(g, 0, 0, base, t);
    for (int ch = 0; ch < nch; ch++) {
        int stg = ch & 1;
        if (ch + 1 < nch) {
            gload(g, ch + 1, stg ^ 1, base, t);
            asm volatile("cp.async.wait_group 1;");
        } else {
            asm volatile("cp.async.wait_group 0;");
        }
        __syncthreads();
        uint32_t sA = base + (uint32_t)stg * 32768u;
        uint32_t sB = sA + 16384u;
#pragma unroll
        for (int s = 0; s < 4; s++) {
            uint32_t a[4][4], b[4][2];
#pragma unroll
            for (int mt = 0; mt < 4; mt++) {
                int row = wr * 64 + mt * 16 + (lane & 15);
                int u = s * 2 + (lane >> 4);
                ldsm4(a[mt], sA + (uint32_t)row * 128u + (uint32_t)((u ^ (row & 7)) << 4));
            }
#pragma unroll
            for (int nt = 0; nt < 4; nt++) {
                int row = wc * 32 + nt * 8 + (lane & 7);
                int u = s * 2 + ((lane >> 3) & 1);
                ldsm2(b[nt], sB + (uint32_t)row * 128u + (uint32_t)((u ^ (row & 7)) << 4));
            }
#pragma unroll
            for (int mt = 0; mt < 4; mt++)
#pragma unroll
                for (int nt = 0; nt < 4; nt++)
                    mma16816(acc[mt][nt], a[mt], b[nt]);
        }
        __syncthreads();
    }
}

#define GEMM_PRE() \
    extern __shared__ char dynsm[]; \
    uint32_t raw = smem_u32(dynsm); \
    uint32_t base = (raw + 127u) & ~127u; \
    float acc[4][4][4]; \
    for (int i = 0; i < 4; i++) for (int j = 0; j < 4; j++) for (int q = 0; q < 4; q++) acc[i][j][q] = 0.f; \
    const int warp = threadIdx.x >> 5, lane = threadIdx.x & 31; \
    const int wr = warp >> 2, wc = warp & 3; \
    const int gr = lane >> 2, gc = lane & 3;

#define MMA_SMEM (65536 + 128)

// ---------------- proj: relu(x@W + bias) -> split low planes ----------------
__global__ __launch_bounds__(256, 2) void proj_mma()
{
    GEMM_PRE();
    int n0 = blockIdx.x * 128, m0 = blockIdx.y * 128;
    GArgs g;
    g.A[0] = g_xh + (size_t)m0 * SS;  g.B[0] = g_WTh + (size_t)n0 * SS;
    g.A[1] = g_xh + (size_t)m0 * SS;  g.B[1] = g_WTl + (size_t)n0 * SS;
    g.A[2] = g_xl + (size_t)m0 * SS;  g.B[2] = g_WTh + (size_t)n0 * SS;
    g.npass = 3; g.kpp = 8; g.lda = SS; g.ldb = SS; g.bvalid = 128;
    gemm_run(g, acc, base);
#pragma unroll
    for (int mt = 0; mt < 4; mt++) {
#pragma unroll
        for (int nt = 0; nt < 4; nt++) {
            int col = n0 + wc * 32 + nt * 8 + gc * 2;
            int p = col / PLW, e = col - p * PLW;
            float b0 = g_bias[col], b1 = g_bias[col + 1];
#pragma unroll
            for (int h = 0; h < 2; h++) {
                int row = m0 + wr * 64 + mt * 16 + gr + h * 8;
                float v0 = fmaxf(acc[mt][nt][h * 2 + 0] + b0, 0.f);
                float v1 = fmaxf(acc[mt][nt][h * 2 + 1] + b1, 0.f);
                size_t d = (size_t)p * PSL + (size_t)row * KP + e;
                hsplit(v0, &g_lowh[d], &g_lowl[d]);
                hsplit(v1, &g_lowh[d + 1], &g_lowl[d + 1]);
            }
        }
    }
}

// ---------------- score: 6 Karatsuba planes (K=256 GEMM + fp32 rank-1 Nyquist) ----------------
__global__ __launch_bounds__(256, 2) void score_mma()
{
    GEMM_PRE();
    __shared__ float sA256[128], sB256[128];
    int z = blockIdx.z;
    int b = z / 6, which = z - b * 6;
    int hi = (which >= 3) ? 1 : 0;
    int w = which - 3 * hi;
    int apn = (w == 2) ? 4 : w;
    int bpn = hi ? ((w == 2) ? 5 : w + 2) : apn;
    int m0 = blockIdx.y * 128, n0 = blockIdx.x * 128;
    if (threadIdx.x < 128)
        sA256[threadIdx.x] = plane256(apn, b * CC + m0 + threadIdx.x);
    else
        sB256[threadIdx.x - 128] = plane256(bpn, b * CC + n0 + threadIdx.x - 128);
    size_t aoff = (size_t)apn * PSL + (size_t)(b * CC + m0) * KP;
    size_t boff = (size_t)bpn * PSL + (size_t)(b * CC + n0) * KP;
    GArgs g;
    g.A[0] = g_lowh + aoff;  g.B[0] = g_lowh + boff;
    g.A[1] = g_lowh + aoff;  g.B[1] = g_lowl + boff;
    g.A[2] = g_lowl + aoff;  g.B[2] = g_lowh + boff;
    g.npass = 3; g.kpp = 4; g.lda = KP; g.ldb = KP; g.bvalid = 128;
    gemm_run(g, acc, base);
    float* out = g_S + (size_t)which * PS + (size_t)(b * CC) * CC;
#pragma unroll
    for (int mt = 0; mt < 4; mt++) {
#pragma unroll
        for (int nt = 0; nt < 4; nt++) {
            int cl = wc * 32 + nt * 8 + gc * 2;
            float bv0 = sB256[cl], bv1 = sB256[cl + 1];
            int col = n0 + cl;
#pragma unroll
            for (int h = 0; h < 2; h++) {
                int rl = wr * 64 + mt * 16 + gr + h * 8;
                float av = sA256[rl];
                int row = m0 + rl;
                *(float2*)&out[(size_t)row * CC + col] =
                    make_float2(acc[mt][nt][h * 2 + 0] + av * bv0,
                                acc[mt][nt][h * 2 + 1] + av * bv1);
            }
        }
    }
}

// ---------------- softmax + Karatsuba combine -> P fp16 [Pr|Pi]; also xr[256] ----------------
__device__ __forceinline__ void softmax16(float (&v)[16])
{
    float m = -3.4e38f;
#pragma unroll
    for (int u = 0; u < 16; u++) m = fmaxf(m, v[u]);
#pragma unroll
    for (int o = 16; o; o >>= 1) m = fmaxf(m, __shfl_xor_sync(0xffffffffu, m, o));
    float s = 0.f;
#pragma unroll
    for (int u = 0; u < 16; u++) { v[u] = expf(v[u] - m); s += v[u]; }
#pragma unroll
    for (int o = 16; o; o >>= 1) s += __shfl_xor_sync(0xffffffffu, s, o);
    float r = 1.f / s;
#pragma unroll
    for (int u = 0; u < 16; u++) v[u] *= r;
}

__global__ void softmax_kernel()
{
    int gw = (blockIdx.x * blockDim.x + threadIdx.x) >> 5;
    int lane = threadIdx.x & 31;
    int b = gw >> 9;
    size_t base = (size_t)gw * CC;
    float t1[16], t2[16], t3[16], sr[16], si[16], pr[16], pi[16];
#pragma unroll
    for (int u = 0; u < 16; u++) {
        int c = lane + u * 32;
        t1[u] = g_S[0 * PS + base + c];
        t2[u] = g_S[1 * PS + base + c];
        t3[u] = g_S[2 * PS + base + c];
    }
#pragma unroll
    for (int u = 0; u < 16; u++) {
        sr[u] = (t1[u] - t2[u]) * ATTN_SCALE;
        si[u] = (t3[u] - t1[u] - t2[u]) * ATTN_SCALE;
    }
    softmax16(sr);
    softmax16(si);
#pragma unroll
    for (int u = 0; u < 16; u++) { pr[u] = sr[u]; pi[u] = si[u]; }
#pragma unroll
    for (int u = 0; u < 16; u++) {
        int c = lane + u * 32;
        t1[u] = g_S[3 * PS + base + c];
        t2[u] = g_S[4 * PS + base + c];
        t3[u] = g_S[5 * PS + base + c];
    }
#pragma unroll
    for (int u = 0; u < 16; u++) {
        sr[u] = (t1[u] - t2[u]) * ATTN_SCALE;
        si[u] = (t3[u] - t1[u] - t2[u]) * ATTN_SCALE;
    }
    softmax16(sr);
    softmax16(si);
    float xr = 0.f;
#pragma unroll
    for (int u = 0; u < 16; u++) {
        int c = lane + u * 32;
        float prf = pr[u] + sr[u], pif = pi[u] + si[u];
        size_t d = (size_t)gw * 1024 + c;
        g_P[d]       = __float2half_rn(prf);
        g_P[d + 512] = __float2half_rn(pif);
        float2 v = *(const float2*)&g_vny[2 * (b * CC + c)];
        xr += prf * v.x - pif * v.y;
    }
#pragma unroll
    for (int o = 16; o; o >>= 1) xr += __shfl_xor_sync(0xffffffffu, xr, o);
    if (lane == 0) g_Xny[gw] = xr;
}

// ---------------- attnv: X = P @ vt^T (single fp16, K=1024), packed N=256/pl ----------------
__global__ __launch_bounds__(256, 2) void attnv_mma()
{
    GEMM_PRE();
    int z = blockIdx.z;
    int b = z >> 1, pl = z & 1;
    int n0 = blockIdx.x * 128, m0 = blockIdx.y * 128;
    GArgs g;
    g.A[0] = g_P + (size_t)(b * CC + m0) * 1024;
    g.B[0] = g_vt + ((size_t)(b * 2 + pl) * 256 + n0) * 1024;
    g.npass = 1; g.kpp = 16; g.lda = 1024; g.ldb = 1024; g.bvalid = 128;
    gemm_run(g, acc, base);
#pragma unroll
    for (int mt = 0; mt < 4; mt++) {
#pragma unroll
        for (int nt = 0; nt < 4; nt++) {
            int col = n0 + wc * 32 + nt * 8 + gc * 2;
#pragma unroll
            for (int h = 0; h < 2; h++) {
                int row = m0 + wr * 64 + mt * 16 + gr + h * 8;
                size_t d = (size_t)(b * CC + row) * XW + (size_t)pl * 256 + col;
                __half2 v = __floats2half2_rn(acc[mt][nt][h * 2 + 0], acc[mt][nt][h * 2 + 1]);
                *(__half2*)&g_X[d] = v;
            }
        }
    }
}

// ---------------- irfft: out = X @ CT^T (K=512) + Nyquist rank-1 ----------------
__global__ __launch_bounds__(256, 2) void irfft_mma(float* __restrict__ out)
{
    GEMM_PRE();
    __shared__ float sXny[128];
    int n0 = blockIdx.x * 128, m0 = blockIdx.y * 128;
    if (threadIdx.x < 128) sXny[threadIdx.x] = g_Xny[m0 + threadIdx.x];
    GArgs g;
    g.A[0] = g_X + (size_t)m0 * XW;
    g.B[0] = g_CT + (size_t)n0 * XW;
    g.npass = 1; g.kpp = 8; g.lda = XW; g.ldb = XW; g.bvalid = 128;
    gemm_run(g, acc, base);
#pragma unroll
    for (int mt = 0; mt < 4; mt++) {
#pragma unroll
        for (int nt = 0; nt < 4; nt++) {
            int col = n0 + wc * 32 + nt * 8 + gc * 2;
            float w0 = (col & 1) ? -INV_SQRT_S : INV_SQRT_S;
#pragma unroll
            for (int h = 0; h < 2; h++) {
                int rl = wr * 64 + mt * 16 + gr + h * 8;
                float xny = sXny[rl];
                int row = m0 + rl;
                *(float2*)&out[(size_t)row * SS + col] =
                    make_float2(acc[mt][nt][h * 2 + 0] + xny * w0,
                                acc[mt][nt][h * 2 + 1] - xny * w0);
            }
        }
    }
}

// ---------------- launch ----------------

extern "C" void kernel_launch(void* const* d_in, const int* in_sizes, int n_in,
                              void* d_out, int out_size)
{
    const float* x   = (const float*)d_in[0];
    const float* l1r = (const float*)d_in[1];
    const float* l1i = (const float*)d_in[2];
    const float* h1r = (const float*)d_in[3];
    const float* h1i = (const float*)d_in[4];
    const float* lbr = (const float*)d_in[5];
    const float* lbi = (const float*)d_in[6];
    const float* hbr = (const float*)d_in[7];
    const float* hbi = (const float*)d_in[8];
    float* out = (float*)d_out;

    cudaFuncSetAttribute(proj_mma,  cudaFuncAttributeMaxDynamicSharedMemorySize, MMA_SMEM);
    cudaFuncSetAttribute(score_mma, cudaFuncAttributeMaxDynamicSharedMemorySize, MMA_SMEM);
    cudaFuncSetAttribute(attnv_mma, cudaFuncAttributeMaxDynamicSharedMemorySize, MMA_SMEM);
    cudaFuncSetAttribute(irfft_mma, cudaFuncAttributeMaxDynamicSharedMemorySize, MMA_SMEM);

    split_x_kernel<<<(int)(((size_t)MTOT * SS + 255) / 256), 256>>>(x);
    build_w_kernel<<<512, 256>>>(l1r, l1i, h1r, h1i);
    build_bias_kernel<<<(NWP + 255) / 256, 256>>>(lbr, lbi, hbr, hbi);
    build_ct_kernel<<<(SS * XW + 255) / 256, 256>>>();
    pad_wt_kernel<<<(4 * 31 * SS + 255) / 256, 256>>>();

    proj_mma<<<dim3(NWP / 128, MTOT / 128), 256, MMA_SMEM>>>();      // (9, 256)
    sum_kernel<<<(int)((PSL + 255) / 256), 256>>>();
    vny_kernel<<<(BB * CC + 255) / 256, 256>>>();
    vt_kernel<<<dim3(CC / 32, 256 / 32, BB), dim3(32, 8)>>>();
    score_mma<<<dim3(4, 4, BB * 6), 256, MMA_SMEM>>>();              // (4, 4, 384)
    softmax_kernel<<<MTOT / 8, 256>>>();
    attnv_mma<<<dim3(2, 4, BB * 2), 256, MMA_SMEM>>>();              // (2, 4, 128)
    irfft_mma<<<dim3(4, MTOT / 128), 256, MMA_SMEM>>>(out);          // (4, 256)
}

// round 8
// speedup vs baseline: 3.5147x; 1.0891x over previous
#include <cuda_runtime.h>
#include <cuda_fp16.h>
#include <cstdint>
#include <math.h>

// ---------------- problem constants ----------------
#define BB 64
#define CC 512
#define SS 512
#define EE 257
#define MTOT (BB*CC)                 // 32768
#define KP  256                      // low-plane row stride (e<256 only)
#define PSL ((size_t)MTOT*KP)
#define NWP 1024                     // proj N = 4*256
#define XW  512                      // packed X row stride / irfft K
#define PS  ((size_t)BB*CC*CC)

#define INV_SQRT_S 0.04419417382415922f
#define TWO_PI_OVER_S 0.01227184630308513f
#define ATTN_SCALE 0.06237828615518053f   // 1/sqrt(257)

// ---------------- scratch (static device globals) ----------------
__device__ __align__(256) float g_bias[NWP];
__device__ __align__(256) float g_Wny[4*SS];          // W column e=256, [p][s]
__device__ __align__(256) float g_ny[4*MTOT];         // low/high @e=256, planar [p][m]
__device__ __align__(256) float g_S[6*PS];
__device__ __align__(256) float g_Xny[MTOT];          // xr at e=256
__device__ __align__(256) __half g_xh[(size_t)MTOT*SS];
__device__ __align__(256) __half g_xl[(size_t)MTOT*SS];
__device__ __align__(256) __half g_WTh[NWP*SS];
__device__ __align__(256) __half g_WTl[NWP*SS];
__device__ __align__(256) __half g_CT[SS*XW];
__device__ __align__(256) __half g_lowh[6*PSL];
__device__ __align__(256) __half g_lowl[6*PSL];
__device__ __align__(256) __half g_P[(size_t)MTOT*1024];
__device__ __align__(256) __half g_vt[(size_t)BB*2*256*1024];
__device__ __align__(256) __half g_X[(size_t)MTOT*XW];

// ---------------- helpers ----------------
__device__ __forceinline__ uint32_t smem_u32(const void* p) {
    uint32_t a;
    asm("{ .reg .u64 t; cvta.to.shared.u64 t, %1; cvt.u32.u64 %0, t; }" : "=r"(a) : "l"(p));
    return a;
}
__device__ __forceinline__ void hsplit(float v, __half* h, __half* l) {
    __half a = __float2half_rn(v);
    *h = a;
    *l = __float2half_rn(v - __half2float(a));
}
__device__ __forceinline__ void ldsm4(uint32_t (&r)[4], uint32_t a) {
    asm volatile("ldmatrix.sync.aligned.m8n8.x4.shared.b16 {%0,%1,%2,%3}, [%4];"
                 : "=r"(r[0]), "=r"(r[1]), "=r"(r[2]), "=r"(r[3]) : "r"(a));
}
__device__ __forceinline__ void ldsm2(uint32_t (&r)[2], uint32_t a) {
    asm volatile("ldmatrix.sync.aligned.m8n8.x2.shared.b16 {%0,%1}, [%2];"
                 : "=r"(r[0]), "=r"(r[1]) : "r"(a));
}
__device__ __forceinline__ void mma16816(float (&d)[4], const uint32_t (&a)[4], const uint32_t (&b)[2]) {
    asm volatile(
        "mma.sync.aligned.m16n8k16.row.col.f32.f16.f16.f32 "
        "{%0,%1,%2,%3},{%4,%5,%6,%7},{%8,%9},{%0,%1,%2,%3};"
        : "+f"(d[0]), "+f"(d[1]), "+f"(d[2]), "+f"(d[3])
        : "r"(a[0]), "r"(a[1]), "r"(a[2]), "r"(a[3]), "r"(b[0]), "r"(b[1]));
}
__device__ __forceinline__ void cpasync16(uint32_t s, const void* g) {
    asm volatile("cp.async.cg.shared.global [%0], [%1], 16;" :: "r"(s), "l"(g));
}
__device__ __forceinline__ float plane256(int pn, int r) {
    if (pn == 4) return g_ny[0 * MTOT + r] + g_ny[1 * MTOT + r];
    if (pn == 5) return g_ny[2 * MTOT + r] + g_ny[3 * MTOT + r];
    return g_ny[pn * MTOT + r];
}

// ---------------- builder kernels ----------------

// W = F_sub @ l1/h1 transposed: WT[(p*256+e)][s] split hi/lo; e=256 column -> g_Wny
__global__ void build_w_kernel(const float* __restrict__ l1r, const float* __restrict__ l1i,
                               const float* __restrict__ h1r, const float* __restrict__ h1i)
{
    __shared__ float cr[257], ci[257];
    int s = blockIdx.x;
    for (int k = threadIdx.x; k < 257; k += blockDim.x) {
        int idx = (s * k) & 511;
        float ang = (float)idx * TWO_PI_OVER_S;
        float sn, cs;
        sincosf(ang, &sn, &cs);
        cr[k] = cs * INV_SQRT_S;
        ci[k] = -sn * INV_SQRT_S;
    }
    __syncthreads();
    for (int e = threadIdx.x; e < EE; e += blockDim.x) {
        float wlr = 0.f, wli = 0.f, whr = 0.f, whi = 0.f;
        for (int k = 0; k < 128; k++) {
            float ar = cr[k], ai = ci[k];
            float br = l1r[k * EE + e], bi = l1i[k * EE + e];
            wlr += ar * br - ai * bi;
            wli += ar * bi + ai * br;
        }
        for (int k = 0; k < 129; k++) {
            float ar = cr[128 + k], ai = ci[128 + k];
            float br = h1r[k * EE + e], bi = h1i[k * EE + e];
            whr += ar * br - ai * bi;
            whi += ar * bi + ai * br;
        }
        if (e < 256) {
            hsplit(wlr, &g_WTh[(0 * 256 + e) * SS + s], &g_WTl[(0 * 256 + e) * SS + s]);
            hsplit(wli, &g_WTh[(1 * 256 + e) * SS + s], &g_WTl[(1 * 256 + e) * SS + s]);
            hsplit(whr, &g_WTh[(2 * 256 + e) * SS + s], &g_WTl[(2 * 256 + e) * SS + s]);
            hsplit(whi, &g_WTh[(3 * 256 + e) * SS + s], &g_WTl[(3 * 256 + e) * SS + s]);
        } else {
            g_Wny[0 * SS + s] = wlr;
            g_Wny[1 * SS + s] = wli;
            g_Wny[2 * SS + s] = whr;
            g_Wny[3 * SS + s] = whi;
        }
    }
}

__global__ void build_bias_kernel(const float* __restrict__ lbr, const float* __restrict__ lbi,
                                  const float* __restrict__ hbr, const float* __restrict__ hbi)
{
    int n = blockIdx.x * blockDim.x + threadIdx.x;
    if (n >= NWP) return;
    int p = n >> 8, e = n & 255;
    const float* src = (p == 0) ? lbr : (p == 1) ? lbi : (p == 2) ? hbr : hbi;
    g_bias[n] = src[e];
}

// split x into fp16 hi/lo AND compute Nyquist projections (exact fp32 rank-1 inputs).
// one warp per row (8 rows per block).
__global__ void splitx_ny_kernel(const float* __restrict__ x,
                                 const float* __restrict__ lbr, const float* __restrict__ lbi,
                                 const float* __restrict__ hbr, const float* __restrict__ hbi)
{
    __shared__ float sW[4][512];
    __shared__ float sb[4];
    int t = threadIdx.x;
    for (int i = t; i < 4 * 512; i += 256) sW[i >> 9][i & 511] = g_Wny[i];
    if (t == 0) { sb[0] = lbr[256]; sb[1] = lbi[256]; sb[2] = hbr[256]; sb[3] = hbi[256]; }
    __syncthreads();
    int warp = t >> 5, lane = t & 31;
    int row = blockIdx.x * 8 + warp;
    const float* xr = x + (size_t)row * SS;
    float a0 = 0.f, a1 = 0.f, a2 = 0.f, a3 = 0.f;
#pragma unroll
    for (int i = 0; i < 4; i++) {
        int s = i * 128 + lane * 4;
        float4 v = *(const float4*)(xr + s);
        float vv[4] = {v.x, v.y, v.z, v.w};
        __half hh[4], ll[4];
#pragma unroll
        for (int j = 0; j < 4; j++) {
            hsplit(vv[j], &hh[j], &ll[j]);
            a0 += vv[j] * sW[0][s + j];
            a1 += vv[j] * sW[1][s + j];
            a2 += vv[j] * sW[2][s + j];
            a3 += vv[j] * sW[3][s + j];
        }
        size_t d = (size_t)row * SS + s;
        *(__half2*)&g_xh[d]     = __halves2half2(hh[0], hh[1]);
        *(__half2*)&g_xh[d + 2] = __halves2half2(hh[2], hh[3]);
        *(__half2*)&g_xl[d]     = __halves2half2(ll[0], ll[1]);
        *(__half2*)&g_xl[d + 2] = __halves2half2(ll[2], ll[3]);
    }
#pragma unroll
    for (int o = 16; o; o >>= 1) {
        a0 += __shfl_xor_sync(0xffffffffu, a0, o);
        a1 += __shfl_xor_sync(0xffffffffu, a1, o);
        a2 += __shfl_xor_sync(0xffffffffu, a2, o);
        a3 += __shfl_xor_sync(0xffffffffu, a3, o);
    }
    if (lane == 0) {
        g_ny[0 * MTOT + row] = fmaxf(a0 + sb[0], 0.f);
        g_ny[1 * MTOT + row] = fmaxf(a1 + sb[1], 0.f);
        g_ny[2 * MTOT + row] = fmaxf(a2 + sb[2], 0.f);
        g_ny[3 * MTOT + row] = fmaxf(a3 + sb[3], 0.f);
    }
}

// packed CT[s][k]: k<256 -> w*cos(e=k), k>=256 -> -2*sin(e=k-256) (e=0 -> 0)
__global__ void build_ct_kernel()
{
    int idx = blockIdx.x * blockDim.x + threadIdx.x;
    if (idx >= SS * XW) return;
    int s = idx / XW, k = idx - s * XW;
    float v;
    if (k < 256) {
        int e = k;
        float w = (e == 0) ? 1.f : 2.f;
        float ang = (float)((e * s) & 511) * TWO_PI_OVER_S;
        v = w * cosf(ang) * INV_SQRT_S;
    } else {
        int e = k - 256;
        if (e == 0) v = 0.f;
        else {
            float ang = (float)((e * s) & 511) * TWO_PI_OVER_S;
            v = -2.f * sinf(ang) * INV_SQRT_S;
        }
    }
    g_CT[idx] = __float2half_rn(v);
}

// sum planes: ls = lr+li (4), hs = hr+hi (5)
__global__ void sum_kernel()
{
    size_t i = (size_t)blockIdx.x * blockDim.x + threadIdx.x;
    if (i >= PSL) return;
    float lr = __half2float(g_lowh[0 * PSL + i]) + __half2float(g_lowl[0 * PSL + i]);
    float li = __half2float(g_lowh[1 * PSL + i]) + __half2float(g_lowl[1 * PSL + i]);
    float hr = __half2float(g_lowh[2 * PSL + i]) + __half2float(g_lowl[2 * PSL + i]);
    float hi = __half2float(g_lowh[3 * PSL + i]) + __half2float(g_lowl[3 * PSL + i]);
    hsplit(lr + li, &g_lowh[4 * PSL + i], &g_lowl[4 * PSL + i]);
    hsplit(hr + hi, &g_lowh[5 * PSL + i], &g_lowl[5 * PSL + i]);
}

// packed vt: vt[b][0][n][k] = [vr | -vi], vt[b][1][n][k] = [vi | vr]; n<256, k<1024
__global__ void vt_kernel()
{
    __shared__ float tr[32][33], ti[32][33];
    int b = blockIdx.z, e0 = blockIdx.y * 32, c0 = blockIdx.x * 32;
    int tx = threadIdx.x, ty = threadIdx.y;
    for (int r = ty; r < 32; r += 8) {
        size_t src = ((size_t)(b * CC + c0 + r)) * KP + (e0 + tx);
        tr[r][tx] = __half2float(g_lowh[0 * PSL + src]) + __half2float(g_lowl[0 * PSL + src]);
        ti[r][tx] = __half2float(g_lowh[1 * PSL + src]) + __half2float(g_lowl[1 * PSL + src]);
    }
    __syncthreads();
    for (int r = ty; r < 32; r += 8) {
        int n = e0 + r, c = c0 + tx;
        float lr = tr[tx][r], li = ti[tx][r];
        size_t d0 = ((size_t)(b * 2 + 0) * 256 + n) * 1024;
        size_t d1 = ((size_t)(b * 2 + 1) * 256 + n) * 1024;
        g_vt[d0 + c]       = __float2half_rn(lr);
        g_vt[d0 + 512 + c] = __float2half_rn(-li);
        g_vt[d1 + c]       = __float2half_rn(li);
        g_vt[d1 + 512 + c] = __float2half_rn(lr);
    }
}

// ---------------- HMMA GEMM core: 128x128 tile, 8 warps, K-chunk 64 ----------------

struct GArgs {
    const __half* A[3];
    const __half* B[3];
    int npass, kpp, lda, ldb, bvalid;
};

__device__ __forceinline__ void gload(const GArgs& g, int ch, int stg, uint32_t base, int t)
{
    int p = ch / g.kpp, kc = ch - p * g.kpp;
    const __half* Ap = g.A[p] + kc * 64;
    const __half* Bp = g.B[p] + kc * 64;
    int r = t >> 1, c4 = (t & 1) * 4;
    int rb = (r < g.bvalid) ? r : (g.bvalid - 1);
    const __half* ga = Ap + (size_t)r * g.lda + c4 * 8;
    const __half* gb = Bp + (size_t)rb * g.ldb + c4 * 8;
    uint32_t sA = base + (uint32_t)stg * 32768u + (uint32_t)r * 128u;
    uint32_t sB = sA + 16384u;
#pragma unroll
    for (int i = 0; i < 4; i++) {
        int c = c4 + i;
        uint32_t sw = (uint32_t)((c ^ (r & 7)) << 4);
        cpasync16(sA + sw, ga + i * 8);
        cpasync16(sB + sw, gb + i * 8);
    }
    asm volatile("cp.async.commit_group;");
}

__device__ __forceinline__ void gemm_run(const GArgs& g, float (&acc)[4][4][4], uint32_t base)
{
    const int t = threadIdx.x;
    const int nch = g.npass * g.kpp;
    const int warp = t >> 5, lane = t & 31;
    const int wr = warp >> 2, wc = warp & 3;

    gload(g, 0, 0, base, t);
    for (int ch = 0; ch < nch; ch++) {
        int stg = ch & 1;
        if (ch + 1 < nch) {
            gload(g, ch + 1, stg ^ 1, base, t);
            asm volatile("cp.async.wait_group 1;");
        } else {
            asm volatile("cp.async.wait_group 0;");
        }
        __syncthreads();
        uint32_t sA = base + (uint32_t)stg * 32768u;
        uint32_t sB = sA + 16384u;
#pragma unroll
        for (int s = 0; s < 4; s++) {
            uint32_t a[4][4], b[4][2];
#pragma unroll
            for (int mt = 0; mt < 4; mt++) {
                int row = wr * 64 + mt * 16 + (lane & 15);
                int u = s * 2 + (lane >> 4);
                ldsm4(a[mt], sA + (uint32_t)row * 128u + (uint32_t)((u ^ (row & 7)) << 4));
            }
#pragma unroll
            for (int nt = 0; nt < 4; nt++) {
                int row = wc * 32 + nt * 8 + (lane & 7);
                int u = s * 2 + ((lane >> 3) & 1);
                ldsm2(b[nt], sB + (uint32_t)row * 128u + (uint32_t)((u ^ (row & 7)) << 4));
            }
#pragma unroll
            for (int mt = 0; mt < 4; mt++)
#pragma unroll
                for (int nt = 0; nt < 4; nt++)
                    mma16816(acc[mt][nt], a[mt], b[nt]);
        }
        __syncthreads();
    }
}

#define GEMM_PRE() \
    extern __shared__ char dynsm[]; \
    uint32_t raw = smem_u32(dynsm); \
    uint32_t base = (raw + 127u) & ~127u; \
    float acc[4][4][4]; \
    for (int i = 0; i < 4; i++) for (int j = 0; j < 4; j++) for (int q = 0; q < 4; q++) acc[i][j][q] = 0.f; \
    const int warp = threadIdx.x >> 5, lane = threadIdx.x & 31; \
    const int wr = warp >> 2, wc = warp & 3; \
    const int gr = lane >> 2, gc = lane & 3;

#define MMA_SMEM (65536 + 128)

// ---------------- proj: relu(x@W + bias) -> split low planes (N=1024) ----------------
__global__ __launch_bounds__(256, 2) void proj_mma()
{
    GEMM_PRE();
    int n0 = blockIdx.x * 128, m0 = blockIdx.y * 128;
    GArgs g;
    g.A[0] = g_xh + (size_t)m0 * SS;  g.B[0] = g_WTh + (size_t)n0 * SS;
    g.A[1] = g_xh + (size_t)m0 * SS;  g.B[1] = g_WTl + (size_t)n0 * SS;
    g.A[2] = g_xl + (size_t)m0 * SS;  g.B[2] = g_WTh + (size_t)n0 * SS;
    g.npass = 3; g.kpp = 8; g.lda = SS; g.ldb = SS; g.bvalid = 128;
    gemm_run(g, acc, base);
#pragma unroll
    for (int mt = 0; mt < 4; mt++) {
#pragma unroll
        for (int nt = 0; nt < 4; nt++) {
            int col = n0 + wc * 32 + nt * 8 + gc * 2;
            int p = col >> 8, e = col & 255;
            float b0 = g_bias[col], b1 = g_bias[col + 1];
#pragma unroll
            for (int h = 0; h < 2; h++) {
                int row = m0 + wr * 64 + mt * 16 + gr + h * 8;
                float v0 = fmaxf(acc[mt][nt][h * 2 + 0] + b0, 0.f);
                float v1 = fmaxf(acc[mt][nt][h * 2 + 1] + b1, 0.f);
                size_t d = (size_t)p * PSL + (size_t)row * KP + e;
                __half h0, l0, h1, l1;
                hsplit(v0, &h0, &l0);
                hsplit(v1, &h1, &l1);
                *(__half2*)&g_lowh[d] = __halves2half2(h0, h1);
                *(__half2*)&g_lowl[d] = __halves2half2(l0, l1);
            }
        }
    }
}

// ---------------- score: 6 Karatsuba planes (K=256 GEMM + fp32 rank-1 Nyquist) ----------------
__global__ __launch_bounds__(256, 2) void score_mma()
{
    GEMM_PRE();
    __shared__ float sA256[128], sB256[128];
    int z = blockIdx.z;
    int b = z / 6, which = z - b * 6;
    int hi = (which >= 3) ? 1 : 0;
    int w = which - 3 * hi;
    int apn = (w == 2) ? 4 : w;
    int bpn = hi ? ((w == 2) ? 5 : w + 2) : apn;
    int m0 = blockIdx.y * 128, n0 = blockIdx.x * 128;
    if (threadIdx.x < 128)
        sA256[threadIdx.x] = plane256(apn, b * CC + m0 + threadIdx.x);
    else
        sB256[threadIdx.x - 128] = plane256(bpn, b * CC + n0 + threadIdx.x - 128);
    size_t aoff = (size_t)apn * PSL + (size_t)(b * CC + m0) * KP;
    size_t boff = (size_t)bpn * PSL + (size_t)(b * CC + n0) * KP;
    GArgs g;
    g.A[0] = g_lowh + aoff;  g.B[0] = g_lowh + boff;
    g.A[1] = g_lowh + aoff;  g.B[1] = g_lowl + boff;
    g.A[2] = g_lowl + aoff;  g.B[2] = g_lowh + boff;
    g.npass = 3; g.kpp = 4; g.lda = KP; g.ldb = KP; g.bvalid = 128;
    gemm_run(g, acc, base);
    float* out = g_S + (size_t)which * PS + (size_t)(b * CC) * CC;
#pragma unroll
    for (int mt = 0; mt < 4; mt++) {
#pragma unroll
        for (int nt = 0; nt < 4; nt++) {
            int cl = wc * 32 + nt * 8 + gc * 2;
            float bv0 = sB256[cl], bv1 = sB256[cl + 1];
            int col = n0 + cl;
#pragma unroll
            for (int h = 0; h < 2; h++) {
                int rl = wr * 64 + mt * 16 + gr + h * 8;
                float av = sA256[rl];
                int row = m0 + rl;
                *(float2*)&out[(size_t)row * CC + col] =
                    make_float2(acc[mt][nt][h * 2 + 0] + av * bv0,
                                acc[mt][nt][h * 2 + 1] + av * bv1);
            }
        }
    }
}

// ---------------- softmax + Karatsuba combine -> P fp16 [Pr|Pi]; also xr[256] ----------------
__device__ __forceinline__ void softmax16(float (&v)[16])
{
    float m = -3.4e38f;
#pragma unroll
    for (int u = 0; u < 16; u++) m = fmaxf(m, v[u]);
#pragma unroll
    for (int o = 16; o; o >>= 1) m = fmaxf(m, __shfl_xor_sync(0xffffffffu, m, o));
    float s = 0.f;
#pragma unroll
    for (int u = 0; u < 16; u++) { v[u] = expf(v[u] - m); s += v[u]; }
#pragma unroll
    for (int o = 16; o; o >>= 1) s += __shfl_xor_sync(0xffffffffu, s, o);
    float r = 1.f / s;
#pragma unroll
    for (int u = 0; u < 16; u++) v[u] *= r;
}

__global__ void softmax_kernel()
{
    int gw = (blockIdx.x * blockDim.x + threadIdx.x) >> 5;
    int lane = threadIdx.x & 31;
    size_t base = (size_t)gw * CC;
    float t1[16], t2[16], t3[16], sr[16], si[16], pr[16], pi[16];
#pragma unroll
    for (int u = 0; u < 16; u++) {
        int c = lane + u * 32;
        t1[u] = g_S[0 * PS + base + c];
        t2[u] = g_S[1 * PS + base + c];
        t3[u] = g_S[2 * PS + base + c];
    }
#pragma unroll
    for (int u = 0; u < 16; u++) {
        sr[u] = (t1[u] - t2[u]) * ATTN_SCALE;
        si[u] = (t3[u] - t1[u] - t2[u]) * ATTN_SCALE;
    }
    softmax16(sr);
    softmax16(si);
#pragma unroll
    for (int u = 0; u < 16; u++) { pr[u] = sr[u]; pi[u] = si[u]; }
#pragma unroll
    for (int u = 0; u < 16; u++) {
        int c = lane + u * 32;
        t1[u] = g_S[3 * PS + base + c];
        t2[u] = g_S[4 * PS + base + c];
        t3[u] = g_S[5 * PS + base + c];
    }
#pragma unroll
    for (int u = 0; u < 16; u++) {
        sr[u] = (t1[u] - t2[u]) * ATTN_SCALE;
        si[u] = (t3[u] - t1[u] - t2[u]) * ATTN_SCALE;
    }
    softmax16(sr);
    softmax16(si);
    int brow = (gw >> 9) << 9;   // b * CC
    float xr = 0.f;
#pragma unroll
    for (int u = 0; u < 16; u++) {
        int c = lane + u * 32;
        float prf = pr[u] + sr[u], pif = pi[u] + si[u];
        size_t d = (size_t)gw * 1024 + c;
        g_P[d]       = __float2half_rn(prf);
        g_P[d + 512] = __float2half_rn(pif);
        xr += prf * g_ny[0 * MTOT + brow + c] - pif * g_ny[1 * MTOT + brow + c];
    }
#pragma unroll
    for (int o = 16; o; o >>= 1) xr += __shfl_xor_sync(0xffffffffu, xr, o);
    if (lane == 0) g_Xny[gw] = xr;
}

// ---------------- attnv: X = P @ vt^T (single fp16, K=1024), packed N=256/pl ----------------
__global__ __launch_bounds__(256, 2) void attnv_mma()
{
    GEMM_PRE();
    int z = blockIdx.z;
    int b = z >> 1, pl = z & 1;
    int n0 = blockIdx.x * 128, m0 = blockIdx.y * 128;
    GArgs g;
    g.A[0] = g_P + (size_t)(b * CC + m0) * 1024;
    g.B[0] = g_vt + ((size_t)(b * 2 + pl) * 256 + n0) * 1024;
    g.npass = 1; g.kpp = 16; g.lda = 1024; g.ldb = 1024; g.bvalid = 128;
    gemm_run(g, acc, base);
#pragma unroll
    for (int mt = 0; mt < 4; mt++) {
#pragma unroll
        for (int nt = 0; nt < 4; nt++) {
            int col = n0 + wc * 32 + nt * 8 + gc * 2;
#pragma unroll
            for (int h = 0; h < 2; h++) {
                int row = m0 + wr * 64 + mt * 16 + gr + h * 8;
                size_t d = (size_t)(b * CC + row) * XW + (size_t)pl * 256 + col;
                __half2 v = __floats2half2_rn(acc[mt][nt][h * 2 + 0], acc[mt][nt][h * 2 + 1]);
                *(__half2*)&g_X[d] = v;
            }
        }
    }
}

// ---------------- irfft: out = X @ CT^T (K=512) + Nyquist rank-1 ----------------
__global__ __launch_bounds__(256, 2) void irfft_mma(float* __restrict__ out)
{
    GEMM_PRE();
    __shared__ float sXny[128];
    int n0 = blockIdx.x * 128, m0 = blockIdx.y * 128;
    if (threadIdx.x < 128) sXny[threadIdx.x] = g_Xny[m0 + threadIdx.x];
    GArgs g;
    g.A[0] = g_X + (size_t)m0 * XW;
    g.B[0] = g_CT + (size_t)n0 * XW;
    g.npass = 1; g.kpp = 8; g.lda = XW; g.ldb = XW; g.bvalid = 128;
    gemm_run(g, acc, base);
#pragma unroll
    for (int mt = 0; mt < 4; mt++) {
#pragma unroll
        for (int nt = 0; nt < 4; nt++) {
            int col = n0 + wc * 32 + nt * 8 + gc * 2;
            float w0 = (col & 1) ? -INV_SQRT_S : INV_SQRT_S;
#pragma unroll
            for (int h = 0; h < 2; h++) {
                int rl = wr * 64 + mt * 16 + gr + h * 8;
                float xny = sXny[rl];
                int row = m0 + rl;
                *(float2*)&out[(size_t)row * SS + col] =
                    make_float2(acc[mt][nt][h * 2 + 0] + xny * w0,
                                acc[mt][nt][h * 2 + 1] - xny * w0);
            }
        }
    }
}

// ---------------- launch ----------------

extern "C" void kernel_launch(void* const* d_in, const int* in_sizes, int n_in,
                              void* d_out, int out_size)
{
    const float* x   = (const float*)d_in[0];
    const float* l1r = (const float*)d_in[1];
    const float* l1i = (const float*)d_in[2];
    const float* h1r = (const float*)d_in[3];
    const float* h1i = (const float*)d_in[4];
    const float* lbr = (const float*)d_in[5];
    const float* lbi = (const float*)d_in[6];
    const float* hbr = (const float*)d_in[7];
    const float* hbi = (const float*)d_in[8];
    float* out = (float*)d_out;

    cudaFuncSetAttribute(proj_mma,  cudaFuncAttributeMaxDynamicSharedMemorySize, MMA_SMEM);
    cudaFuncSetAttribute(score_mma, cudaFuncAttributeMaxDynamicSharedMemorySize, MMA_SMEM);
    cudaFuncSetAttribute(attnv_mma, cudaFuncAttributeMaxDynamicSharedMemorySize, MMA_SMEM);
    cudaFuncSetAttribute(irfft_mma, cudaFuncAttributeMaxDynamicSharedMemorySize, MMA_SMEM);

    // launch order chosen so ncu (-s 5 -c 1) profiles score_mma (index 5)
    build_w_kernel<<<512, 256>>>(l1r, l1i, h1r, h1i);                        // 0
    build_bias_kernel<<<(NWP + 255) / 256, 256>>>(lbr, lbi, hbr, hbi);       // 1
    splitx_ny_kernel<<<MTOT / 8, 256>>>(x, lbr, lbi, hbr, hbi);              // 2
    proj_mma<<<dim3(NWP / 128, MTOT / 128), 256, MMA_SMEM>>>();              // 3 (8, 256)
    sum_kernel<<<(int)((PSL + 255) / 256), 256>>>();                         // 4
    score_mma<<<dim3(4, 4, BB * 6), 256, MMA_SMEM>>>();                      // 5 <- profiled
    softmax_kernel<<<MTOT / 8, 256>>>();                                     // 6
    vt_kernel<<<dim3(CC / 32, 256 / 32, BB), dim3(32, 8)>>>();               // 7
    build_ct_kernel<<<(SS * XW + 255) / 256, 256>>>();                       // 8
    attnv_mma<<<dim3(2, 4, BB * 2), 256, MMA_SMEM>>>();                      // 9
    irfft_mma<<<dim3(4, MTOT / 128), 256, MMA_SMEM>>>(out);                  // 10
}

// round 9
// speedup vs baseline: 3.6411x; 1.0360x over previous
#include <cuda_runtime.h>
#include <cuda_fp16.h>
#include <cstdint>
#include <math.h>

// ---------------- problem constants ----------------
#define BB 64
#define CC 512
#define SS 512
#define EE 257
#define MTOT (BB*CC)                 // 32768
#define KP  256                      // low-plane row stride (e<256 only)
#define PSL ((size_t)MTOT*KP)
#define NWP 1024                     // proj N = 4*256
#define XW  512                      // packed X row stride / irfft K
#define PS  ((size_t)BB*CC*CC)

#define INV_SQRT_S 0.04419417382415922f
#define TWO_PI_OVER_S 0.01227184630308513f
#define ATTN_SCALE 0.06237828615518053f   // 1/sqrt(257)

// ---------------- scratch (static device globals) ----------------
__device__ __align__(256) float g_bias[NWP];
__device__ __align__(256) float g_Wny[4*SS];          // W column e=256, [p][s]
__device__ __align__(256) float g_ny[4*MTOT];         // low/high @e=256, planar [p][m]
__device__ __align__(256) float g_S[6*PS];
__device__ __align__(256) float g_Xny[MTOT];          // xr at e=256
__device__ __align__(256) __half g_xh[(size_t)MTOT*SS];
__device__ __align__(256) __half g_xl[(size_t)MTOT*SS];
__device__ __align__(256) __half g_WTh[NWP*SS];
__device__ __align__(256) __half g_WTl[NWP*SS];
__device__ __align__(256) __half g_CT[SS*XW];
__device__ __align__(256) __half g_lowh[6*PSL];
__device__ __align__(256) __half g_lowl[6*PSL];
__device__ __align__(256) __half g_P[(size_t)MTOT*1024];
__device__ __align__(256) __half g_vt[(size_t)BB*2*256*1024];
__device__ __align__(256) __half g_X[(size_t)MTOT*XW];

// ---------------- helpers ----------------
__device__ __forceinline__ uint32_t smem_u32(const void* p) {
    uint32_t a;
    asm("{ .reg .u64 t; cvta.to.shared.u64 t, %1; cvt.u32.u64 %0, t; }" : "=r"(a) : "l"(p));
    return a;
}
__device__ __forceinline__ void hsplit(float v, __half* h, __half* l) {
    __half a = __float2half_rn(v);
    *h = a;
    *l = __float2half_rn(v - __half2float(a));
}
__device__ __forceinline__ void ldsm4(uint32_t (&r)[4], uint32_t a) {
    asm volatile("ldmatrix.sync.aligned.m8n8.x4.shared.b16 {%0,%1,%2,%3}, [%4];"
                 : "=r"(r[0]), "=r"(r[1]), "=r"(r[2]), "=r"(r[3]) : "r"(a));
}
__device__ __forceinline__ void mma16816b(float (&d)[4], const uint32_t (&a)[4],
                                          uint32_t b0, uint32_t b1) {
    asm volatile(
        "mma.sync.aligned.m16n8k16.row.col.f32.f16.f16.f32 "
        "{%0,%1,%2,%3},{%4,%5,%6,%7},{%8,%9},{%0,%1,%2,%3};"
        : "+f"(d[0]), "+f"(d[1]), "+f"(d[2]), "+f"(d[3])
        : "r"(a[0]), "r"(a[1]), "r"(a[2]), "r"(a[3]), "r"(b0), "r"(b1));
}
__device__ __forceinline__ void cpasync16(uint32_t s, const void* g) {
    asm volatile("cp.async.cg.shared.global [%0], [%1], 16;" :: "r"(s), "l"(g));
}
__device__ __forceinline__ float plane256(int pn, int r) {
    if (pn == 4) return g_ny[0 * MTOT + r] + g_ny[1 * MTOT + r];
    if (pn == 5) return g_ny[2 * MTOT + r] + g_ny[3 * MTOT + r];
    return g_ny[pn * MTOT + r];
}

// ---------------- builder kernels ----------------

// W = F_sub @ l1/h1 transposed: WT[(p*256+e)][s] split hi/lo; e=256 column -> g_Wny
__global__ void build_w_kernel(const float* __restrict__ l1r, const float* __restrict__ l1i,
                               const float* __restrict__ h1r, const float* __restrict__ h1i)
{
    __shared__ float cr[257], ci[257];
    int s = blockIdx.x;
    for (int k = threadIdx.x; k < 257; k += blockDim.x) {
        int idx = (s * k) & 511;
        float ang = (float)idx * TWO_PI_OVER_S;
        float sn, cs;
        sincosf(ang, &sn, &cs);
        cr[k] = cs * INV_SQRT_S;
        ci[k] = -sn * INV_SQRT_S;
    }
    __syncthreads();
    for (int e = threadIdx.x; e < EE; e += blockDim.x) {
        float wlr = 0.f, wli = 0.f, whr = 0.f, whi = 0.f;
        for (int k = 0; k < 128; k++) {
            float ar = cr[k], ai = ci[k];
            float br = l1r[k * EE + e], bi = l1i[k * EE + e];
            wlr += ar * br - ai * bi;
            wli += ar * bi + ai * br;
        }
        for (int k = 0; k < 129; k++) {
            float ar = cr[128 + k], ai = ci[128 + k];
            float br = h1r[k * EE + e], bi = h1i[k * EE + e];
            whr += ar * br - ai * bi;
            whi += ar * bi + ai * br;
        }
        if (e < 256) {
            hsplit(wlr, &g_WTh[(0 * 256 + e) * SS + s], &g_WTl[(0 * 256 + e) * SS + s]);
            hsplit(wli, &g_WTh[(1 * 256 + e) * SS + s], &g_WTl[(1 * 256 + e) * SS + s]);
            hsplit(whr, &g_WTh[(2 * 256 + e) * SS + s], &g_WTl[(2 * 256 + e) * SS + s]);
            hsplit(whi, &g_WTh[(3 * 256 + e) * SS + s], &g_WTl[(3 * 256 + e) * SS + s]);
        } else {
            g_Wny[0 * SS + s] = wlr;
            g_Wny[1 * SS + s] = wli;
            g_Wny[2 * SS + s] = whr;
            g_Wny[3 * SS + s] = whi;
        }
    }
}

__global__ void build_bias_kernel(const float* __restrict__ lbr, const float* __restrict__ lbi,
                                  const float* __restrict__ hbr, const float* __restrict__ hbi)
{
    int n = blockIdx.x * blockDim.x + threadIdx.x;
    if (n >= NWP) return;
    int p = n >> 8, e = n & 255;
    const float* src = (p == 0) ? lbr : (p == 1) ? lbi : (p == 2) ? hbr : hbi;
    g_bias[n] = src[e];
}

// split x into fp16 hi/lo AND compute Nyquist projections (exact fp32 rank-1 inputs).
__global__ void splitx_ny_kernel(const float* __restrict__ x,
                                 const float* __restrict__ lbr, const float* __restrict__ lbi,
                                 const float* __restrict__ hbr, const float* __restrict__ hbi)
{
    __shared__ float sW[4][512];
    __shared__ float sb[4];
    int t = threadIdx.x;
    for (int i = t; i < 4 * 512; i += 256) sW[i >> 9][i & 511] = g_Wny[i];
    if (t == 0) { sb[0] = lbr[256]; sb[1] = lbi[256]; sb[2] = hbr[256]; sb[3] = hbi[256]; }
    __syncthreads();
    int warp = t >> 5, lane = t & 31;
    int row = blockIdx.x * 8 + warp;
    const float* xr = x + (size_t)row * SS;
    float a0 = 0.f, a1 = 0.f, a2 = 0.f, a3 = 0.f;
#pragma unroll
    for (int i = 0; i < 4; i++) {
        int s = i * 128 + lane * 4;
        float4 v = *(const float4*)(xr + s);
        float vv[4] = {v.x, v.y, v.z, v.w};
        __half hh[4], ll[4];
#pragma unroll
        for (int j = 0; j < 4; j++) {
            hsplit(vv[j], &hh[j], &ll[j]);
            a0 += vv[j] * sW[0][s + j];
            a1 += vv[j] * sW[1][s + j];
            a2 += vv[j] * sW[2][s + j];
            a3 += vv[j] * sW[3][s + j];
        }
        size_t d = (size_t)row * SS + s;
        *(__half2*)&g_xh[d]     = __halves2half2(hh[0], hh[1]);
        *(__half2*)&g_xh[d + 2] = __halves2half2(hh[2], hh[3]);
        *(__half2*)&g_xl[d]     = __halves2half2(ll[0], ll[1]);
        *(__half2*)&g_xl[d + 2] = __halves2half2(ll[2], ll[3]);
    }
#pragma unroll
    for (int o = 16; o; o >>= 1) {
        a0 += __shfl_xor_sync(0xffffffffu, a0, o);
        a1 += __shfl_xor_sync(0xffffffffu, a1, o);
        a2 += __shfl_xor_sync(0xffffffffu, a2, o);
        a3 += __shfl_xor_sync(0xffffffffu, a3, o);
    }
    if (lane == 0) {
        g_ny[0 * MTOT + row] = fmaxf(a0 + sb[0], 0.f);
        g_ny[1 * MTOT + row] = fmaxf(a1 + sb[1], 0.f);
        g_ny[2 * MTOT + row] = fmaxf(a2 + sb[2], 0.f);
        g_ny[3 * MTOT + row] = fmaxf(a3 + sb[3], 0.f);
    }
}

// packed CT[s][k]: k<256 -> w*cos(e=k), k>=256 -> -2*sin(e=k-256) (e=0 -> 0)
__global__ void build_ct_kernel()
{
    int idx = blockIdx.x * blockDim.x + threadIdx.x;
    if (idx >= SS * XW) return;
    int s = idx / XW, k = idx - s * XW;
    float v;
    if (k < 256) {
        int e = k;
        float w = (e == 0) ? 1.f : 2.f;
        float ang = (float)((e * s) & 511) * TWO_PI_OVER_S;
        v = w * cosf(ang) * INV_SQRT_S;
    } else {
        int e = k - 256;
        if (e == 0) v = 0.f;
        else {
            float ang = (float)((e * s) & 511) * TWO_PI_OVER_S;
            v = -2.f * sinf(ang) * INV_SQRT_S;
        }
    }
    g_CT[idx] = __float2half_rn(v);
}

// sum planes: ls = lr+li (4), hs = hr+hi (5)
__global__ void sum_kernel()
{
    size_t i = (size_t)blockIdx.x * blockDim.x + threadIdx.x;
    if (i >= PSL) return;
    float lr = __half2float(g_lowh[0 * PSL + i]) + __half2float(g_lowl[0 * PSL + i]);
    float li = __half2float(g_lowh[1 * PSL + i]) + __half2float(g_lowl[1 * PSL + i]);
    float hr = __half2float(g_lowh[2 * PSL + i]) + __half2float(g_lowl[2 * PSL + i]);
    float hi = __half2float(g_lowh[3 * PSL + i]) + __half2float(g_lowl[3 * PSL + i]);
    hsplit(lr + li, &g_lowh[4 * PSL + i], &g_lowl[4 * PSL + i]);
    hsplit(hr + hi, &g_lowh[5 * PSL + i], &g_lowl[5 * PSL + i]);
}

// packed vt: vt[b][0][n][k] = [vr | -vi], vt[b][1][n][k] = [vi | vr]; n<256, k<1024
__global__ void vt_kernel()
{
    __shared__ float tr[32][33], ti[32][33];
    int b = blockIdx.z, e0 = blockIdx.y * 32, c0 = blockIdx.x * 32;
    int tx = threadIdx.x, ty = threadIdx.y;
    for (int r = ty; r < 32; r += 8) {
        size_t src = ((size_t)(b * CC + c0 + r)) * KP + (e0 + tx);
        tr[r][tx] = __half2float(g_lowh[0 * PSL + src]) + __half2float(g_lowl[0 * PSL + src]);
        ti[r][tx] = __half2float(g_lowh[1 * PSL + src]) + __half2float(g_lowl[1 * PSL + src]);
    }
    __syncthreads();
    for (int r = ty; r < 32; r += 8) {
        int n = e0 + r, c = c0 + tx;
        float lr = tr[tx][r], li = ti[tx][r];
        size_t d0 = ((size_t)(b * 2 + 0) * 256 + n) * 1024;
        size_t d1 = ((size_t)(b * 2 + 1) * 256 + n) * 1024;
        g_vt[d0 + c]       = __float2half_rn(lr);
        g_vt[d0 + 512 + c] = __float2half_rn(-li);
        g_vt[d1 + c]       = __float2half_rn(li);
        g_vt[d1 + 512 + c] = __float2half_rn(lr);
    }
}

// ---------------- HMMA GEMM core: 128x128 tile, 8 warps, K-chunk 64 ----------------
// 3-stage cp.async pipeline, one barrier per chunk, paired-B ldmatrix.

struct GArgs {
    const __half* A[3];
    const __half* B[3];
    int npass, kpp, lda, ldb, bvalid;
};

__device__ __forceinline__ void gload(const GArgs& g, int ch, int stg, uint32_t base, int t)
{
    int p = ch / g.kpp, kc = ch - p * g.kpp;
    const __half* Ap = g.A[p] + kc * 64;
    const __half* Bp = g.B[p] + kc * 64;
    int r = t >> 1, c4 = (t & 1) * 4;
    int rb = (r < g.bvalid) ? r : (g.bvalid - 1);
    const __half* ga = Ap + (size_t)r * g.lda + c4 * 8;
    const __half* gb = Bp + (size_t)rb * g.ldb + c4 * 8;
    uint32_t sA = base + (uint32_t)stg * 32768u + (uint32_t)r * 128u;
    uint32_t sB = sA + 16384u;
#pragma unroll
    for (int i = 0; i < 4; i++) {
        int c = c4 + i;
        uint32_t sw = (uint32_t)((c ^ (r & 7)) << 4);
        cpasync16(sA + sw, ga + i * 8);
        cpasync16(sB + sw, gb + i * 8);
    }
    asm volatile("cp.async.commit_group;");
}

__device__ __forceinline__ void gemm_run(const GArgs& g, float (&acc)[4][4][4], uint32_t base)
{
    const int t = threadIdx.x;
    const int nch = g.npass * g.kpp;
    const int warp = t >> 5, lane = t & 31;
    const int wr = warp >> 2, wc = warp & 3;

    gload(g, 0, 0, base, t);
    if (nch > 1) gload(g, 1, 1, base, t);
    for (int ch = 0; ch < nch; ch++) {
        int stg = ch - (ch / 3) * 3;
        if (ch + 1 < nch) asm volatile("cp.async.wait_group 1;");
        else              asm volatile("cp.async.wait_group 0;");
        __syncthreads();
        if (ch + 2 < nch) gload(g, ch + 2, (ch + 2) % 3, base, t);
        uint32_t sA = base + (uint32_t)stg * 32768u;
        uint32_t sB = sA + 16384u;
#pragma unroll
        for (int s = 0; s < 4; s++) {
            uint32_t a[4][4], b[2][4];
#pragma unroll
            for (int mt = 0; mt < 4; mt++) {
                int row = wr * 64 + mt * 16 + (lane & 15);
                int u = s * 2 + (lane >> 4);
                ldsm4(a[mt], sA + (uint32_t)row * 128u + (uint32_t)((u ^ (row & 7)) << 4));
            }
#pragma unroll
            for (int ntp = 0; ntp < 2; ntp++) {
                int row = wc * 32 + ntp * 16 + (((lane >> 4) & 1) << 3) + (lane & 7);
                int u = s * 2 + ((lane >> 3) & 1);
                ldsm4(b[ntp], sB + (uint32_t)row * 128u + (uint32_t)((u ^ (row & 7)) << 4));
            }
#pragma unroll
            for (int mt = 0; mt < 4; mt++)
#pragma unroll
                for (int nt = 0; nt < 4; nt++)
                    mma16816b(acc[mt][nt], a[mt], b[nt >> 1][(nt & 1) * 2],
                              b[nt >> 1][(nt & 1) * 2 + 1]);
        }
    }
    __syncthreads();
}

#define GEMM_PRE() \
    extern __shared__ char dynsm[]; \
    uint32_t raw = smem_u32(dynsm); \
    uint32_t base = (raw + 127u) & ~127u; \
    float acc[4][4][4]; \
    for (int i = 0; i < 4; i++) for (int j = 0; j < 4; j++) for (int q = 0; q < 4; q++) acc[i][j][q] = 0.f; \
    const int warp = threadIdx.x >> 5, lane = threadIdx.x & 31; \
    const int wr = warp >> 2, wc = warp & 3; \
    const int gr = lane >> 2, gc = lane & 3;

#define MMA_SMEM (3 * 32768 + 128)

// ---------------- proj: relu(x@W + bias) -> split low planes (N=1024) ----------------
__global__ __launch_bounds__(256, 2) void proj_mma()
{
    GEMM_PRE();
    int n0 = blockIdx.x * 128, m0 = blockIdx.y * 128;
    GArgs g;
    g.A[0] = g_xh + (size_t)m0 * SS;  g.B[0] = g_WTh + (size_t)n0 * SS;
    g.A[1] = g_xh + (size_t)m0 * SS;  g.B[1] = g_WTl + (size_t)n0 * SS;
    g.A[2] = g_xl + (size_t)m0 * SS;  g.B[2] = g_WTh + (size_t)n0 * SS;
    g.npass = 3; g.kpp = 8; g.lda = SS; g.ldb = SS; g.bvalid = 128;
    gemm_run(g, acc, base);
#pragma unroll
    for (int mt = 0; mt < 4; mt++) {
#pragma unroll
        for (int nt = 0; nt < 4; nt++) {
            int col = n0 + wc * 32 + nt * 8 + gc * 2;
            int p = col >> 8, e = col & 255;
            float b0 = g_bias[col], b1 = g_bias[col + 1];
#pragma unroll
            for (int h = 0; h < 2; h++) {
                int row = m0 + wr * 64 + mt * 16 + gr + h * 8;
                float v0 = fmaxf(acc[mt][nt][h * 2 + 0] + b0, 0.f);
                float v1 = fmaxf(acc[mt][nt][h * 2 + 1] + b1, 0.f);
                size_t d = (size_t)p * PSL + (size_t)row * KP + e;
                __half h0, l0, h1, l1;
                hsplit(v0, &h0, &l0);
                hsplit(v1, &h1, &l1);
                *(__half2*)&g_lowh[d] = __halves2half2(h0, h1);
                *(__half2*)&g_lowl[d] = __halves2half2(l0, l1);
            }
        }
    }
}

// ---------------- score: 6 Karatsuba planes (K=256 GEMM + fp32 rank-1 Nyquist) ----------------
__global__ __launch_bounds__(256, 2) void score_mma()
{
    GEMM_PRE();
    __shared__ float sA256[128], sB256[128];
    int z = blockIdx.z;
    int b = z / 6, which = z - b * 6;
    int hi = (which >= 3) ? 1 : 0;
    int w = which - 3 * hi;
    int apn = (w == 2) ? 4 : w;
    int bpn = hi ? ((w == 2) ? 5 : w + 2) : apn;
    int m0 = blockIdx.y * 128, n0 = blockIdx.x * 128;
    if (threadIdx.x < 128)
        sA256[threadIdx.x] = plane256(apn, b * CC + m0 + threadIdx.x);
    else
        sB256[threadIdx.x - 128] = plane256(bpn, b * CC + n0 + threadIdx.x - 128);
    size_t aoff = (size_t)apn * PSL + (size_t)(b * CC + m0) * KP;
    size_t boff = (size_t)bpn * PSL + (size_t)(b * CC + n0) * KP;
    GArgs g;
    g.A[0] = g_lowh + aoff;  g.B[0] = g_lowh + boff;
    g.A[1] = g_lowh + aoff;  g.B[1] = g_lowl + boff;
    g.A[2] = g_lowl + aoff;  g.B[2] = g_lowh + boff;
    g.npass = 3; g.kpp = 4; g.lda = KP; g.ldb = KP; g.bvalid = 128;
    gemm_run(g, acc, base);
    float* out = g_S + (size_t)which * PS + (size_t)(b * CC) * CC;
#pragma unroll
    for (int mt = 0; mt < 4; mt++) {
#pragma unroll
        for (int nt = 0; nt < 4; nt++) {
            int cl = wc * 32 + nt * 8 + gc * 2;
            float bv0 = sB256[cl], bv1 = sB256[cl + 1];
            int col = n0 + cl;
#pragma unroll
            for (int h = 0; h < 2; h++) {
                int rl = wr * 64 + mt * 16 + gr + h * 8;
                float av = sA256[rl];
                int row = m0 + rl;
                *(float2*)&out[(size_t)row * CC + col] =
                    make_float2(acc[mt][nt][h * 2 + 0] + av * bv0,
                                acc[mt][nt][h * 2 + 1] + av * bv1);
            }
        }
    }
}

// ---------------- softmax + Karatsuba combine -> P fp16 [Pr|Pi]; also xr[256] ----------------
__device__ __forceinline__ void softmax16(float (&v)[16])
{
    float m = -3.4e38f;
#pragma unroll
    for (int u = 0; u < 16; u++) m = fmaxf(m, v[u]);
#pragma unroll
    for (int o = 16; o; o >>= 1) m = fmaxf(m, __shfl_xor_sync(0xffffffffu, m, o));
    float s = 0.f;
#pragma unroll
    for (int u = 0; u < 16; u++) { v[u] = expf(v[u] - m); s += v[u]; }
#pragma unroll
    for (int o = 16; o; o >>= 1) s += __shfl_xor_sync(0xffffffffu, s, o);
    float r = 1.f / s;
#pragma unroll
    for (int u = 0; u < 16; u++) v[u] *= r;
}

__global__ void softmax_kernel()
{
    int gw = (blockIdx.x * blockDim.x + threadIdx.x) >> 5;
    int lane = threadIdx.x & 31;
    size_t base = (size_t)gw * CC;
    float t1[16], t2[16], t3[16], sr[16], si[16], pr[16], pi[16];
#pragma unroll
    for (int u = 0; u < 16; u++) {
        int c = lane + u * 32;
        t1[u] = g_S[0 * PS + base + c];
        t2[u] = g_S[1 * PS + base + c];
        t3[u] = g_S[2 * PS + base + c];
    }
#pragma unroll
    for (int u = 0; u < 16; u++) {
        sr[u] = (t1[u] - t2[u]) * ATTN_SCALE;
        si[u] = (t3[u] - t1[u] - t2[u]) * ATTN_SCALE;
    }
    softmax16(sr);
    softmax16(si);
#pragma unroll
    for (int u = 0; u < 16; u++) { pr[u] = sr[u]; pi[u] = si[u]; }
#pragma unroll
    for (int u = 0; u < 16; u++) {
        int c = lane + u * 32;
        t1[u] = g_S[3 * PS + base + c];
        t2[u] = g_S[4 * PS + base + c];
        t3[u] = g_S[5 * PS + base + c];
    }
#pragma unroll
    for (int u = 0; u < 16; u++) {
        sr[u] = (t1[u] - t2[u]) * ATTN_SCALE;
        si[u] = (t3[u] - t1[u] - t2[u]) * ATTN_SCALE;
    }
    softmax16(sr);
    softmax16(si);
    int brow = (gw >> 9) << 9;   // b * CC
    float xr = 0.f;
#pragma unroll
    for (int u = 0; u < 16; u++) {
        int c = lane + u * 32;
        float prf = pr[u] + sr[u], pif = pi[u] + si[u];
        size_t d = (size_t)gw * 1024 + c;
        g_P[d]       = __float2half_rn(prf);
        g_P[d + 512] = __float2half_rn(pif);
        xr += prf * g_ny[0 * MTOT + brow + c] - pif * g_ny[1 * MTOT + brow + c];
    }
#pragma unroll
    for (int o = 16; o; o >>= 1) xr += __shfl_xor_sync(0xffffffffu, xr, o);
    if (lane == 0) g_Xny[gw] = xr;
}

// ---------------- attnv: X = P @ vt^T (single fp16, K=1024), packed N=256/pl ----------------
__global__ __launch_bounds__(256, 2) void attnv_mma()
{
    GEMM_PRE();
    int z = blockIdx.z;
    int b = z >> 1, pl = z & 1;
    int n0 = blockIdx.x * 128, m0 = blockIdx.y * 128;
    GArgs g;
    g.A[0] = g_P + (size_t)(b * CC + m0) * 1024;
    g.B[0] = g_vt + ((size_t)(b * 2 + pl) * 256 + n0) * 1024;
    g.npass = 1; g.kpp = 16; g.lda = 1024; g.ldb = 1024; g.bvalid = 128;
    gemm_run(g, acc, base);
#pragma unroll
    for (int mt = 0; mt < 4; mt++) {
#pragma unroll
        for (int nt = 0; nt < 4; nt++) {
            int col = n0 + wc * 32 + nt * 8 + gc * 2;
#pragma unroll
            for (int h = 0; h < 2; h++) {
                int row = m0 + wr * 64 + mt * 16 + gr + h * 8;
                size_t d = (size_t)(b * CC + row) * XW + (size_t)pl * 256 + col;
                __half2 v = __floats2half2_rn(acc[mt][nt][h * 2 + 0], acc[mt][nt][h * 2 + 1]);
                *(__half2*)&g_X[d] = v;
            }
        }
    }
}

// ---------------- irfft: out = X @ CT^T (K=512) + Nyquist rank-1 ----------------
__global__ __launch_bounds__(256, 2) void irfft_mma(float* __restrict__ out)
{
    GEMM_PRE();
    __shared__ float sXny[128];
    int n0 = blockIdx.x * 128, m0 = blockIdx.y * 128;
    if (threadIdx.x < 128) sXny[threadIdx.x] = g_Xny[m0 + threadIdx.x];
    GArgs g;
    g.A[0] = g_X + (size_t)m0 * XW;
    g.B[0] = g_CT + (size_t)n0 * XW;
    g.npass = 1; g.kpp = 8; g.lda = XW; g.ldb = XW; g.bvalid = 128;
    gemm_run(g, acc, base);
#pragma unroll
    for (int mt = 0; mt < 4; mt++) {
#pragma unroll
        for (int nt = 0; nt < 4; nt++) {
            int col = n0 + wc * 32 + nt * 8 + gc * 2;
            float w0 = (col & 1) ? -INV_SQRT_S : INV_SQRT_S;
#pragma unroll
            for (int h = 0; h < 2; h++) {
                int rl = wr * 64 + mt * 16 + gr + h * 8;
                float xny = sXny[rl];
                int row = m0 + rl;
                *(float2*)&out[(size_t)row * SS + col] =
                    make_float2(acc[mt][nt][h * 2 + 0] + xny * w0,
                                acc[mt][nt][h * 2 + 1] - xny * w0);
            }
        }
    }
}

// ---------------- launch ----------------

extern "C" void kernel_launch(void* const* d_in, const int* in_sizes, int n_in,
                              void* d_out, int out_size)
{
    const float* x   = (const float*)d_in[0];
    const float* l1r = (const float*)d_in[1];
    const float* l1i = (const float*)d_in[2];
    const float* h1r = (const float*)d_in[3];
    const float* h1i = (const float*)d_in[4];
    const float* lbr = (const float*)d_in[5];
    const float* lbi = (const float*)d_in[6];
    const float* hbr = (const float*)d_in[7];
    const float* hbi = (const float*)d_in[8];
    float* out = (float*)d_out;

    cudaFuncSetAttribute(proj_mma,  cudaFuncAttributeMaxDynamicSharedMemorySize, MMA_SMEM);
    cudaFuncSetAttribute(score_mma, cudaFuncAttributeMaxDynamicSharedMemorySize, MMA_SMEM);
    cudaFuncSetAttribute(attnv_mma, cudaFuncAttributeMaxDynamicSharedMemorySize, MMA_SMEM);
    cudaFuncSetAttribute(irfft_mma, cudaFuncAttributeMaxDynamicSharedMemorySize, MMA_SMEM);

    // launch order chosen so ncu (-s 5 -c 1) profiles score_mma (index 5)
    build_w_kernel<<<512, 256>>>(l1r, l1i, h1r, h1i);                        // 0
    build_bias_kernel<<<(NWP + 255) / 256, 256>>>(lbr, lbi, hbr, hbi);       // 1
    splitx_ny_kernel<<<MTOT / 8, 256>>>(x, lbr, lbi, hbr, hbi);              // 2
    proj_mma<<<dim3(NWP / 128, MTOT / 128), 256, MMA_SMEM>>>();              // 3 (8, 256)
    sum_kernel<<<(int)((PSL + 255) / 256), 256>>>();                         // 4
    score_mma<<<dim3(4, 4, BB * 6), 256, MMA_SMEM>>>();                      // 5 <- profiled
    softmax_kernel<<<MTOT / 8, 256>>>();                                     // 6
    vt_kernel<<<dim3(CC / 32, 256 / 32, BB), dim3(32, 8)>>>();               // 7
    build_ct_kernel<<<(SS * XW + 255) / 256, 256>>>();                       // 8
    attnv_mma<<<dim3(2, 4, BB * 2), 256, MMA_SMEM>>>();                      // 9
    irfft_mma<<<dim3(4, MTOT / 128), 256, MMA_SMEM>>>(out);                  // 10
}